// round 2
// baseline (speedup 1.0000x reference)
#include <cuda_runtime.h>
#include <math.h>

#define MREL 8
#define DDIM 256
#define MAXN 51200

// Scratch (no cudaMalloc allowed): 4 x 52.4 MB
__device__ float g_zsum[(size_t)MAXN * DDIM];
__device__ float g_zmax[(size_t)MAXN * DDIM];
__device__ float g_zagr[(size_t)MAXN * DDIM];
__device__ float g_zpre[(size_t)MAXN * DDIM];

typedef unsigned long long u64;

__device__ __forceinline__ u64 pack2(float lo, float hi) {
    u64 r; asm("mov.b64 %0, {%1, %2};" : "=l"(r) : "f"(lo), "f"(hi)); return r;
}
__device__ __forceinline__ void unpack2(u64 v, float &lo, float &hi) {
    asm("mov.b64 {%0, %1}, %2;" : "=f"(lo), "=f"(hi) : "l"(v));
}
// Packed dual-FMA: d.lo += a.lo*b.lo ; d.hi += a.hi*b.hi  (sm_103a f32x2 path)
__device__ __forceinline__ void fma2(u64 &d, u64 a, u64 b) {
    asm("fma.rn.f32x2 %0, %1, %2, %0;" : "+l"(d) : "l"(a), "l"(b));
}

// ============================================================================
// Kernel 1: gate (softmax over relations) + z_sum.  One warp per node.
// cat[n, m*D+d] = zs[m,n,d];  logits[n,j] = sum cat*Wb[:,j] + bb[j]
// ============================================================================
__global__ void k_gate_zsum(const float* __restrict__ zs,
                            const float* __restrict__ Wb,
                            const float* __restrict__ bb,
                            int N) {
    extern __shared__ float swb[];  // 2048*8 floats = 64 KB
    int tid = threadIdx.x;
    for (int i = tid; i < (MREL * DDIM * MREL) / 4; i += blockDim.x)
        ((float4*)swb)[i] = ((const float4*)Wb)[i];
    __syncthreads();

    int lane = tid & 31;
    int wid  = tid >> 5;
    int warps_per_block = blockDim.x >> 5;
    int stride = warps_per_block * gridDim.x;

    float bbv[8];
#pragma unroll
    for (int j = 0; j < 8; j++) bbv[j] = bb[j];

    for (int n = blockIdx.x * warps_per_block + wid; n < N; n += stride) {
        float vals[MREL][8];
#pragma unroll
        for (int m = 0; m < MREL; m++) {
            const float* p = zs + ((size_t)m * N + n) * DDIM + lane * 8;
            float4 v0 = *(const float4*)p;
            float4 v1 = *(const float4*)(p + 4);
            vals[m][0] = v0.x; vals[m][1] = v0.y; vals[m][2] = v0.z; vals[m][3] = v0.w;
            vals[m][4] = v1.x; vals[m][5] = v1.y; vals[m][6] = v1.z; vals[m][7] = v1.w;
        }
        float lg[8] = {0.f,0.f,0.f,0.f,0.f,0.f,0.f,0.f};
#pragma unroll
        for (int m = 0; m < MREL; m++) {
#pragma unroll
            for (int dd = 0; dd < 8; dd++) {
                const float* w = swb + (size_t)(m * DDIM + lane * 8 + dd) * 8;
                float4 w0 = *(const float4*)w;
                float4 w1 = *(const float4*)(w + 4);
                float v = vals[m][dd];
                lg[0] = fmaf(v, w0.x, lg[0]); lg[1] = fmaf(v, w0.y, lg[1]);
                lg[2] = fmaf(v, w0.z, lg[2]); lg[3] = fmaf(v, w0.w, lg[3]);
                lg[4] = fmaf(v, w1.x, lg[4]); lg[5] = fmaf(v, w1.y, lg[5]);
                lg[6] = fmaf(v, w1.z, lg[6]); lg[7] = fmaf(v, w1.w, lg[7]);
            }
        }
#pragma unroll
        for (int off = 16; off > 0; off >>= 1) {
#pragma unroll
            for (int j = 0; j < 8; j++)
                lg[j] += __shfl_xor_sync(0xffffffffu, lg[j], off);
        }
        float mx = -1e30f;
#pragma unroll
        for (int j = 0; j < 8; j++) { lg[j] += bbv[j]; mx = fmaxf(mx, lg[j]); }
        float g[8], se = 0.f;
#pragma unroll
        for (int j = 0; j < 8; j++) { g[j] = expf(lg[j] - mx); se += g[j]; }
        float inv = 1.f / se;
        float o[8];
#pragma unroll
        for (int dd = 0; dd < 8; dd++) {
            float a = 0.f;
#pragma unroll
            for (int m = 0; m < MREL; m++) a = fmaf(g[m], vals[m][dd], a);
            o[dd] = a * inv;
        }
        float* q = g_zsum + (size_t)n * DDIM + lane * 8;
        *(float4*)q       = make_float4(o[0], o[1], o[2], o[3]);
        *(float4*)(q + 4) = make_float4(o[4], o[5], o[6], o[7]);
    }
}

// ============================================================================
// Kernel 2: the heavy part. For each relation m: proj = zs[m]@Wmax[m]+bmax[m],
// phi = zs[m]@Wphi[m]+bphi[m]; fold z_max = max_m proj, s1 = sum phi,
// s2 = sum phi^2; write z_max and z_agr = 0.5*(s1^2 - s2).
// Tiled 64(nodes) x 64(out) x 16(k), dual-GEMM sharing the A operand,
// inner loop in packed f32x2.
// ============================================================================
__global__ void __launch_bounds__(256, 2) k_maxphi(
        const float* __restrict__ zs,
        const float* __restrict__ Wmax, const float* __restrict__ bmax,
        const float* __restrict__ Wphi, const float* __restrict__ bphi,
        int N) {
    __shared__ float As[16][68];
    __shared__ float Bm[16][64];
    __shared__ float Bp[16][64];

    int tid = threadIdx.x;
    int tx = tid & 15, ty = tid >> 4;
    int n0 = blockIdx.x * 64;
    int e0 = blockIdx.y * 64;

    float cmax[4][4], cs1[4][4], cs2[4][4];
#pragma unroll
    for (int r = 0; r < 4; r++)
#pragma unroll
        for (int c = 0; c < 4; c++) { cmax[r][c] = -1e30f; cs1[r][c] = 0.f; cs2[r][c] = 0.f; }

    int ai = tid >> 2;
    int ak = (tid & 3) * 4;
    const bool aval = (n0 + ai) < N;

    for (int m = 0; m < MREL; m++) {
        u64 accP[4][2], accF[4][2];
#pragma unroll
        for (int r = 0; r < 4; r++) { accP[r][0] = accP[r][1] = 0ull; accF[r][0] = accF[r][1] = 0ull; }

        const float* za = zs + (size_t)m * N * DDIM + (size_t)(aval ? (n0 + ai) : 0) * DDIM + ak;
        const float* wm = Wmax + (size_t)m * DDIM * DDIM + (size_t)ty * DDIM + e0 + tx * 4;
        const float* wp = Wphi + (size_t)m * DDIM * DDIM + (size_t)ty * DDIM + e0 + tx * 4;

        for (int k0 = 0; k0 < DDIM; k0 += 16) {
            float4 av = make_float4(0.f, 0.f, 0.f, 0.f);
            if (aval) av = *(const float4*)(za + k0);
            As[ak + 0][ai] = av.x; As[ak + 1][ai] = av.y;
            As[ak + 2][ai] = av.z; As[ak + 3][ai] = av.w;
            *(float4*)&Bm[ty][tx * 4] = *(const float4*)(wm + (size_t)k0 * DDIM);
            *(float4*)&Bp[ty][tx * 4] = *(const float4*)(wp + (size_t)k0 * DDIM);
            __syncthreads();
#pragma unroll
            for (int kk = 0; kk < 16; kk++) {
                float4 a = *(const float4*)&As[kk][ty * 4];
                u64 ap0 = pack2(a.x, a.x), ap1 = pack2(a.y, a.y);
                u64 ap2 = pack2(a.z, a.z), ap3 = pack2(a.w, a.w);
                ulonglong2 bm2 = *(const ulonglong2*)&Bm[kk][tx * 4];
                ulonglong2 bp2 = *(const ulonglong2*)&Bp[kk][tx * 4];
                fma2(accP[0][0], ap0, bm2.x); fma2(accP[0][1], ap0, bm2.y);
                fma2(accP[1][0], ap1, bm2.x); fma2(accP[1][1], ap1, bm2.y);
                fma2(accP[2][0], ap2, bm2.x); fma2(accP[2][1], ap2, bm2.y);
                fma2(accP[3][0], ap3, bm2.x); fma2(accP[3][1], ap3, bm2.y);
                fma2(accF[0][0], ap0, bp2.x); fma2(accF[0][1], ap0, bp2.y);
                fma2(accF[1][0], ap1, bp2.x); fma2(accF[1][1], ap1, bp2.y);
                fma2(accF[2][0], ap2, bp2.x); fma2(accF[2][1], ap2, bp2.y);
                fma2(accF[3][0], ap3, bp2.x); fma2(accF[3][1], ap3, bp2.y);
            }
            __syncthreads();
        }
        float bmv[4], bpv[4];
#pragma unroll
        for (int c = 0; c < 4; c++) {
            bmv[c] = __ldg(bmax + m * DDIM + e0 + tx * 4 + c);
            bpv[c] = __ldg(bphi + m * DDIM + e0 + tx * 4 + c);
        }
#pragma unroll
        for (int r = 0; r < 4; r++) {
            float p[4], f[4];
            unpack2(accP[r][0], p[0], p[1]); unpack2(accP[r][1], p[2], p[3]);
            unpack2(accF[r][0], f[0], f[1]); unpack2(accF[r][1], f[2], f[3]);
#pragma unroll
            for (int c = 0; c < 4; c++) {
                float pv = p[c] + bmv[c];
                cmax[r][c] = fmaxf(cmax[r][c], pv);
                float fv = f[c] + bpv[c];
                cs1[r][c] += fv;
                cs2[r][c] = fmaf(fv, fv, cs2[r][c]);
            }
        }
    }
#pragma unroll
    for (int r = 0; r < 4; r++) {
        int n = n0 + ty * 4 + r;
        if (n < N) {
            size_t off = (size_t)n * DDIM + e0 + tx * 4;
            *(float4*)(g_zmax + off) =
                make_float4(cmax[r][0], cmax[r][1], cmax[r][2], cmax[r][3]);
            float a0 = 0.5f * (cs1[r][0] * cs1[r][0] - cs2[r][0]);
            float a1 = 0.5f * (cs1[r][1] * cs1[r][1] - cs2[r][1]);
            float a2 = 0.5f * (cs1[r][2] * cs1[r][2] - cs2[r][2]);
            float a3 = 0.5f * (cs1[r][3] * cs1[r][3] - cs2[r][3]);
            *(float4*)(g_zagr + off) = make_float4(a0, a1, a2, a3);
        }
    }
}

// ============================================================================
// Kernel 3: z_pre = concat(z_sum, z_max, z_agr) @ Wc + bc.  K = 768.
// ============================================================================
__global__ void __launch_bounds__(256, 2) k_combine(
        const float* __restrict__ Wc, const float* __restrict__ bc, int N) {
    __shared__ float As[16][68];
    __shared__ float Bs[16][64];

    int tid = threadIdx.x;
    int tx = tid & 15, ty = tid >> 4;
    int n0 = blockIdx.x * 64;
    int e0 = blockIdx.y * 64;

    u64 acc[4][2];
#pragma unroll
    for (int r = 0; r < 4; r++) { acc[r][0] = 0ull; acc[r][1] = 0ull; }

    int ai = tid >> 2;
    int ak = (tid & 3) * 4;
    const bool aval = (n0 + ai) < N;
    size_t arow = (size_t)(aval ? (n0 + ai) : 0) * DDIM + ak;

    for (int k0 = 0; k0 < 3 * DDIM; k0 += 16) {
        const float* src = (k0 < DDIM) ? g_zsum : (k0 < 2 * DDIM) ? g_zmax : g_zagr;
        int kc = k0 & (DDIM - 1);
        float4 av = make_float4(0.f, 0.f, 0.f, 0.f);
        if (aval) av = *(const float4*)(src + arow + kc);
        As[ak + 0][ai] = av.x; As[ak + 1][ai] = av.y;
        As[ak + 2][ai] = av.z; As[ak + 3][ai] = av.w;
        *(float4*)&Bs[ty][tx * 4] = *(const float4*)(Wc + (size_t)(k0 + ty) * DDIM + e0 + tx * 4);
        __syncthreads();
#pragma unroll
        for (int kk = 0; kk < 16; kk++) {
            float4 a = *(const float4*)&As[kk][ty * 4];
            u64 ap0 = pack2(a.x, a.x), ap1 = pack2(a.y, a.y);
            u64 ap2 = pack2(a.z, a.z), ap3 = pack2(a.w, a.w);
            ulonglong2 b2 = *(const ulonglong2*)&Bs[kk][tx * 4];
            fma2(acc[0][0], ap0, b2.x); fma2(acc[0][1], ap0, b2.y);
            fma2(acc[1][0], ap1, b2.x); fma2(acc[1][1], ap1, b2.y);
            fma2(acc[2][0], ap2, b2.x); fma2(acc[2][1], ap2, b2.y);
            fma2(acc[3][0], ap3, b2.x); fma2(acc[3][1], ap3, b2.y);
        }
        __syncthreads();
    }
    float bcv[4];
#pragma unroll
    for (int c = 0; c < 4; c++) bcv[c] = __ldg(bc + e0 + tx * 4 + c);
#pragma unroll
    for (int r = 0; r < 4; r++) {
        int n = n0 + ty * 4 + r;
        if (n < N) {
            float v[4];
            unpack2(acc[r][0], v[0], v[1]); unpack2(acc[r][1], v[2], v[3]);
            size_t off = (size_t)n * DDIM + e0 + tx * 4;
            *(float4*)(g_zpre + off) =
                make_float4(v[0] + bcv[0], v[1] + bcv[1], v[2] + bcv[2], v[3] + bcv[3]);
        }
    }
}

// ============================================================================
// Kernel 4: LayerNorm.  One warp per node.
// ============================================================================
__global__ void k_ln(const float* __restrict__ gamma, const float* __restrict__ beta,
                     float* __restrict__ out, int N) {
    int tid = threadIdx.x;
    int lane = tid & 31;
    int wid = tid >> 5;
    int n = blockIdx.x * (blockDim.x >> 5) + wid;
    if (n >= N) return;

    const float* p = g_zpre + (size_t)n * DDIM + lane * 8;
    float4 v0 = *(const float4*)p;
    float4 v1 = *(const float4*)(p + 4);
    float v[8] = {v0.x, v0.y, v0.z, v0.w, v1.x, v1.y, v1.z, v1.w};
    float s = 0.f, q = 0.f;
#pragma unroll
    for (int dd = 0; dd < 8; dd++) { s += v[dd]; q = fmaf(v[dd], v[dd], q); }
#pragma unroll
    for (int off = 16; off > 0; off >>= 1) {
        s += __shfl_xor_sync(0xffffffffu, s, off);
        q += __shfl_xor_sync(0xffffffffu, q, off);
    }
    float mean = s * (1.f / 256.f);
    float var = q * (1.f / 256.f) - mean * mean;
    float inv = rsqrtf(var + 1e-5f);

    const float* gp = gamma + lane * 8;
    const float* bp = beta + lane * 8;
    float4 g0 = *(const float4*)gp, g1 = *(const float4*)(gp + 4);
    float4 b0 = *(const float4*)bp, b1 = *(const float4*)(bp + 4);
    float g[8] = {g0.x, g0.y, g0.z, g0.w, g1.x, g1.y, g1.z, g1.w};
    float b[8] = {b0.x, b0.y, b0.z, b0.w, b1.x, b1.y, b1.z, b1.w};
    float o[8];
#pragma unroll
    for (int dd = 0; dd < 8; dd++) o[dd] = fmaf((v[dd] - mean) * inv, g[dd], b[dd]);

    float* qo = out + (size_t)n * DDIM + lane * 8;
    *(float4*)qo       = make_float4(o[0], o[1], o[2], o[3]);
    *(float4*)(qo + 4) = make_float4(o[4], o[5], o[6], o[7]);
}

// ============================================================================
extern "C" void kernel_launch(void* const* d_in, const int* in_sizes, int n_in,
                              void* d_out, int out_size) {
    const float* zs    = (const float*)d_in[0];
    const float* Wb    = (const float*)d_in[1];
    const float* bb    = (const float*)d_in[2];
    const float* Wmax  = (const float*)d_in[3];
    const float* bmax  = (const float*)d_in[4];
    const float* Wphi  = (const float*)d_in[5];
    const float* bphi  = (const float*)d_in[6];
    const float* Wc    = (const float*)d_in[7];
    const float* bc    = (const float*)d_in[8];
    const float* gamma = (const float*)d_in[9];
    const float* beta  = (const float*)d_in[10];
    float* out = (float*)d_out;

    int N = in_sizes[0] / (MREL * DDIM);

    cudaFuncSetAttribute(k_gate_zsum, cudaFuncAttributeMaxDynamicSharedMemorySize, 65536);
    k_gate_zsum<<<592, 256, 65536>>>(zs, Wb, bb, N);

    dim3 g2((N + 63) / 64, DDIM / 64);
    k_maxphi<<<g2, 256>>>(zs, Wmax, bmax, Wphi, bphi, N);
    k_combine<<<g2, 256>>>(Wc, bc, N);

    k_ln<<<(N + 7) / 8, 256>>>(gamma, beta, out, N);
}

// round 3
// speedup vs baseline: 1.0001x; 1.0001x over previous
#include <cuda_runtime.h>
#include <math.h>

#define MREL 8
#define DDIM 256
#define MAXN 51200

// Scratch (no cudaMalloc allowed): 4 x 52.4 MB
__device__ float g_zsum[(size_t)MAXN * DDIM];
__device__ float g_zmax[(size_t)MAXN * DDIM];
__device__ float g_zagr[(size_t)MAXN * DDIM];
__device__ float g_zpre[(size_t)MAXN * DDIM];

typedef unsigned long long u64;

__device__ __forceinline__ u64 pack2(float lo, float hi) {
    u64 r; asm("mov.b64 %0, {%1, %2};" : "=l"(r) : "f"(lo), "f"(hi)); return r;
}
__device__ __forceinline__ void unpack2(u64 v, float &lo, float &hi) {
    asm("mov.b64 {%0, %1}, %2;" : "=f"(lo), "=f"(hi) : "l"(v));
}
// Packed dual-FMA: d.lo += a.lo*b.lo ; d.hi += a.hi*b.hi  (sm_103a f32x2 path)
__device__ __forceinline__ void fma2(u64 &d, u64 a, u64 b) {
    asm("fma.rn.f32x2 %0, %1, %2, %0;" : "+l"(d) : "l"(a), "l"(b));
}

// ============================================================================
// Kernel 1: gate (softmax over relations) + z_sum.  One warp per node.
// cat[n, m*D+d] = zs[m,n,d];  logits[n,j] = sum cat*Wb[:,j] + bb[j]
// ============================================================================
__global__ void k_gate_zsum(const float* __restrict__ zs,
                            const float* __restrict__ Wb,
                            const float* __restrict__ bb,
                            int N) {
    extern __shared__ float swb[];  // 2048*8 floats = 64 KB
    int tid = threadIdx.x;
    for (int i = tid; i < (MREL * DDIM * MREL) / 4; i += blockDim.x)
        ((float4*)swb)[i] = ((const float4*)Wb)[i];
    __syncthreads();

    int lane = tid & 31;
    int wid  = tid >> 5;
    int warps_per_block = blockDim.x >> 5;
    int stride = warps_per_block * gridDim.x;

    float bbv[8];
#pragma unroll
    for (int j = 0; j < 8; j++) bbv[j] = bb[j];

    for (int n = blockIdx.x * warps_per_block + wid; n < N; n += stride) {
        float vals[MREL][8];
#pragma unroll
        for (int m = 0; m < MREL; m++) {
            const float* p = zs + ((size_t)m * N + n) * DDIM + lane * 8;
            float4 v0 = *(const float4*)p;
            float4 v1 = *(const float4*)(p + 4);
            vals[m][0] = v0.x; vals[m][1] = v0.y; vals[m][2] = v0.z; vals[m][3] = v0.w;
            vals[m][4] = v1.x; vals[m][5] = v1.y; vals[m][6] = v1.z; vals[m][7] = v1.w;
        }
        float lg[8] = {0.f,0.f,0.f,0.f,0.f,0.f,0.f,0.f};
#pragma unroll
        for (int m = 0; m < MREL; m++) {
#pragma unroll
            for (int dd = 0; dd < 8; dd++) {
                const float* w = swb + (size_t)(m * DDIM + lane * 8 + dd) * 8;
                float4 w0 = *(const float4*)w;
                float4 w1 = *(const float4*)(w + 4);
                float v = vals[m][dd];
                lg[0] = fmaf(v, w0.x, lg[0]); lg[1] = fmaf(v, w0.y, lg[1]);
                lg[2] = fmaf(v, w0.z, lg[2]); lg[3] = fmaf(v, w0.w, lg[3]);
                lg[4] = fmaf(v, w1.x, lg[4]); lg[5] = fmaf(v, w1.y, lg[5]);
                lg[6] = fmaf(v, w1.z, lg[6]); lg[7] = fmaf(v, w1.w, lg[7]);
            }
        }
#pragma unroll
        for (int off = 16; off > 0; off >>= 1) {
#pragma unroll
            for (int j = 0; j < 8; j++)
                lg[j] += __shfl_xor_sync(0xffffffffu, lg[j], off);
        }
        float mx = -1e30f;
#pragma unroll
        for (int j = 0; j < 8; j++) { lg[j] += bbv[j]; mx = fmaxf(mx, lg[j]); }
        float g[8], se = 0.f;
#pragma unroll
        for (int j = 0; j < 8; j++) { g[j] = expf(lg[j] - mx); se += g[j]; }
        float inv = 1.f / se;
        float o[8];
#pragma unroll
        for (int dd = 0; dd < 8; dd++) {
            float a = 0.f;
#pragma unroll
            for (int m = 0; m < MREL; m++) a = fmaf(g[m], vals[m][dd], a);
            o[dd] = a * inv;
        }
        float* q = g_zsum + (size_t)n * DDIM + lane * 8;
        *(float4*)q       = make_float4(o[0], o[1], o[2], o[3]);
        *(float4*)(q + 4) = make_float4(o[4], o[5], o[6], o[7]);
    }
}

// ============================================================================
// Kernel 2: the heavy part. For each relation m: proj = zs[m]@Wmax[m]+bmax[m],
// phi = zs[m]@Wphi[m]+bphi[m]; fold z_max = max_m proj, s1 = sum phi,
// s2 = sum phi^2; write z_max and z_agr = 0.5*(s1^2 - s2).
// Tiled 64(nodes) x 64(out) x 16(k), dual-GEMM sharing the A operand,
// inner loop in packed f32x2.
// ============================================================================
__global__ void __launch_bounds__(256, 2) k_maxphi(
        const float* __restrict__ zs,
        const float* __restrict__ Wmax, const float* __restrict__ bmax,
        const float* __restrict__ Wphi, const float* __restrict__ bphi,
        int N) {
    __shared__ float As[16][68];
    __shared__ float Bm[16][64];
    __shared__ float Bp[16][64];

    int tid = threadIdx.x;
    int tx = tid & 15, ty = tid >> 4;
    int n0 = blockIdx.x * 64;
    int e0 = blockIdx.y * 64;

    float cmax[4][4], cs1[4][4], cs2[4][4];
#pragma unroll
    for (int r = 0; r < 4; r++)
#pragma unroll
        for (int c = 0; c < 4; c++) { cmax[r][c] = -1e30f; cs1[r][c] = 0.f; cs2[r][c] = 0.f; }

    int ai = tid >> 2;
    int ak = (tid & 3) * 4;
    const bool aval = (n0 + ai) < N;

    for (int m = 0; m < MREL; m++) {
        u64 accP[4][2], accF[4][2];
#pragma unroll
        for (int r = 0; r < 4; r++) { accP[r][0] = accP[r][1] = 0ull; accF[r][0] = accF[r][1] = 0ull; }

        const float* za = zs + (size_t)m * N * DDIM + (size_t)(aval ? (n0 + ai) : 0) * DDIM + ak;
        const float* wm = Wmax + (size_t)m * DDIM * DDIM + (size_t)ty * DDIM + e0 + tx * 4;
        const float* wp = Wphi + (size_t)m * DDIM * DDIM + (size_t)ty * DDIM + e0 + tx * 4;

        for (int k0 = 0; k0 < DDIM; k0 += 16) {
            float4 av = make_float4(0.f, 0.f, 0.f, 0.f);
            if (aval) av = *(const float4*)(za + k0);
            As[ak + 0][ai] = av.x; As[ak + 1][ai] = av.y;
            As[ak + 2][ai] = av.z; As[ak + 3][ai] = av.w;
            *(float4*)&Bm[ty][tx * 4] = *(const float4*)(wm + (size_t)k0 * DDIM);
            *(float4*)&Bp[ty][tx * 4] = *(const float4*)(wp + (size_t)k0 * DDIM);
            __syncthreads();
#pragma unroll
            for (int kk = 0; kk < 16; kk++) {
                float4 a = *(const float4*)&As[kk][ty * 4];
                u64 ap0 = pack2(a.x, a.x), ap1 = pack2(a.y, a.y);
                u64 ap2 = pack2(a.z, a.z), ap3 = pack2(a.w, a.w);
                ulonglong2 bm2 = *(const ulonglong2*)&Bm[kk][tx * 4];
                ulonglong2 bp2 = *(const ulonglong2*)&Bp[kk][tx * 4];
                fma2(accP[0][0], ap0, bm2.x); fma2(accP[0][1], ap0, bm2.y);
                fma2(accP[1][0], ap1, bm2.x); fma2(accP[1][1], ap1, bm2.y);
                fma2(accP[2][0], ap2, bm2.x); fma2(accP[2][1], ap2, bm2.y);
                fma2(accP[3][0], ap3, bm2.x); fma2(accP[3][1], ap3, bm2.y);
                fma2(accF[0][0], ap0, bp2.x); fma2(accF[0][1], ap0, bp2.y);
                fma2(accF[1][0], ap1, bp2.x); fma2(accF[1][1], ap1, bp2.y);
                fma2(accF[2][0], ap2, bp2.x); fma2(accF[2][1], ap2, bp2.y);
                fma2(accF[3][0], ap3, bp2.x); fma2(accF[3][1], ap3, bp2.y);
            }
            __syncthreads();
        }
        float bmv[4], bpv[4];
#pragma unroll
        for (int c = 0; c < 4; c++) {
            bmv[c] = __ldg(bmax + m * DDIM + e0 + tx * 4 + c);
            bpv[c] = __ldg(bphi + m * DDIM + e0 + tx * 4 + c);
        }
#pragma unroll
        for (int r = 0; r < 4; r++) {
            float p[4], f[4];
            unpack2(accP[r][0], p[0], p[1]); unpack2(accP[r][1], p[2], p[3]);
            unpack2(accF[r][0], f[0], f[1]); unpack2(accF[r][1], f[2], f[3]);
#pragma unroll
            for (int c = 0; c < 4; c++) {
                float pv = p[c] + bmv[c];
                cmax[r][c] = fmaxf(cmax[r][c], pv);
                float fv = f[c] + bpv[c];
                cs1[r][c] += fv;
                cs2[r][c] = fmaf(fv, fv, cs2[r][c]);
            }
        }
    }
#pragma unroll
    for (int r = 0; r < 4; r++) {
        int n = n0 + ty * 4 + r;
        if (n < N) {
            size_t off = (size_t)n * DDIM + e0 + tx * 4;
            *(float4*)(g_zmax + off) =
                make_float4(cmax[r][0], cmax[r][1], cmax[r][2], cmax[r][3]);
            float a0 = 0.5f * (cs1[r][0] * cs1[r][0] - cs2[r][0]);
            float a1 = 0.5f * (cs1[r][1] * cs1[r][1] - cs2[r][1]);
            float a2 = 0.5f * (cs1[r][2] * cs1[r][2] - cs2[r][2]);
            float a3 = 0.5f * (cs1[r][3] * cs1[r][3] - cs2[r][3]);
            *(float4*)(g_zagr + off) = make_float4(a0, a1, a2, a3);
        }
    }
}

// ============================================================================
// Kernel 3: z_pre = concat(z_sum, z_max, z_agr) @ Wc + bc.  K = 768.
// ============================================================================
__global__ void __launch_bounds__(256, 2) k_combine(
        const float* __restrict__ Wc, const float* __restrict__ bc, int N) {
    __shared__ float As[16][68];
    __shared__ float Bs[16][64];

    int tid = threadIdx.x;
    int tx = tid & 15, ty = tid >> 4;
    int n0 = blockIdx.x * 64;
    int e0 = blockIdx.y * 64;

    u64 acc[4][2];
#pragma unroll
    for (int r = 0; r < 4; r++) { acc[r][0] = 0ull; acc[r][1] = 0ull; }

    int ai = tid >> 2;
    int ak = (tid & 3) * 4;
    const bool aval = (n0 + ai) < N;
    size_t arow = (size_t)(aval ? (n0 + ai) : 0) * DDIM + ak;

    for (int k0 = 0; k0 < 3 * DDIM; k0 += 16) {
        const float* src = (k0 < DDIM) ? g_zsum : (k0 < 2 * DDIM) ? g_zmax : g_zagr;
        int kc = k0 & (DDIM - 1);
        float4 av = make_float4(0.f, 0.f, 0.f, 0.f);
        if (aval) av = *(const float4*)(src + arow + kc);
        As[ak + 0][ai] = av.x; As[ak + 1][ai] = av.y;
        As[ak + 2][ai] = av.z; As[ak + 3][ai] = av.w;
        *(float4*)&Bs[ty][tx * 4] = *(const float4*)(Wc + (size_t)(k0 + ty) * DDIM + e0 + tx * 4);
        __syncthreads();
#pragma unroll
        for (int kk = 0; kk < 16; kk++) {
            float4 a = *(const float4*)&As[kk][ty * 4];
            u64 ap0 = pack2(a.x, a.x), ap1 = pack2(a.y, a.y);
            u64 ap2 = pack2(a.z, a.z), ap3 = pack2(a.w, a.w);
            ulonglong2 b2 = *(const ulonglong2*)&Bs[kk][tx * 4];
            fma2(acc[0][0], ap0, b2.x); fma2(acc[0][1], ap0, b2.y);
            fma2(acc[1][0], ap1, b2.x); fma2(acc[1][1], ap1, b2.y);
            fma2(acc[2][0], ap2, b2.x); fma2(acc[2][1], ap2, b2.y);
            fma2(acc[3][0], ap3, b2.x); fma2(acc[3][1], ap3, b2.y);
        }
        __syncthreads();
    }
    float bcv[4];
#pragma unroll
    for (int c = 0; c < 4; c++) bcv[c] = __ldg(bc + e0 + tx * 4 + c);
#pragma unroll
    for (int r = 0; r < 4; r++) {
        int n = n0 + ty * 4 + r;
        if (n < N) {
            float v[4];
            unpack2(acc[r][0], v[0], v[1]); unpack2(acc[r][1], v[2], v[3]);
            size_t off = (size_t)n * DDIM + e0 + tx * 4;
            *(float4*)(g_zpre + off) =
                make_float4(v[0] + bcv[0], v[1] + bcv[1], v[2] + bcv[2], v[3] + bcv[3]);
        }
    }
}

// ============================================================================
// Kernel 4: LayerNorm.  One warp per node.
// ============================================================================
__global__ void k_ln(const float* __restrict__ gamma, const float* __restrict__ beta,
                     float* __restrict__ out, int N) {
    int tid = threadIdx.x;
    int lane = tid & 31;
    int wid = tid >> 5;
    int n = blockIdx.x * (blockDim.x >> 5) + wid;
    if (n >= N) return;

    const float* p = g_zpre + (size_t)n * DDIM + lane * 8;
    float4 v0 = *(const float4*)p;
    float4 v1 = *(const float4*)(p + 4);
    float v[8] = {v0.x, v0.y, v0.z, v0.w, v1.x, v1.y, v1.z, v1.w};
    float s = 0.f, q = 0.f;
#pragma unroll
    for (int dd = 0; dd < 8; dd++) { s += v[dd]; q = fmaf(v[dd], v[dd], q); }
#pragma unroll
    for (int off = 16; off > 0; off >>= 1) {
        s += __shfl_xor_sync(0xffffffffu, s, off);
        q += __shfl_xor_sync(0xffffffffu, q, off);
    }
    float mean = s * (1.f / 256.f);
    float var = q * (1.f / 256.f) - mean * mean;
    float inv = rsqrtf(var + 1e-5f);

    const float* gp = gamma + lane * 8;
    const float* bp = beta + lane * 8;
    float4 g0 = *(const float4*)gp, g1 = *(const float4*)(gp + 4);
    float4 b0 = *(const float4*)bp, b1 = *(const float4*)(bp + 4);
    float g[8] = {g0.x, g0.y, g0.z, g0.w, g1.x, g1.y, g1.z, g1.w};
    float b[8] = {b0.x, b0.y, b0.z, b0.w, b1.x, b1.y, b1.z, b1.w};
    float o[8];
#pragma unroll
    for (int dd = 0; dd < 8; dd++) o[dd] = fmaf((v[dd] - mean) * inv, g[dd], b[dd]);

    float* qo = out + (size_t)n * DDIM + lane * 8;
    *(float4*)qo       = make_float4(o[0], o[1], o[2], o[3]);
    *(float4*)(qo + 4) = make_float4(o[4], o[5], o[6], o[7]);
}

// ============================================================================
extern "C" void kernel_launch(void* const* d_in, const int* in_sizes, int n_in,
                              void* d_out, int out_size) {
    const float* zs    = (const float*)d_in[0];
    const float* Wb    = (const float*)d_in[1];
    const float* bb    = (const float*)d_in[2];
    const float* Wmax  = (const float*)d_in[3];
    const float* bmax  = (const float*)d_in[4];
    const float* Wphi  = (const float*)d_in[5];
    const float* bphi  = (const float*)d_in[6];
    const float* Wc    = (const float*)d_in[7];
    const float* bc    = (const float*)d_in[8];
    const float* gamma = (const float*)d_in[9];
    const float* beta  = (const float*)d_in[10];
    float* out = (float*)d_out;

    int N = in_sizes[0] / (MREL * DDIM);

    cudaFuncSetAttribute(k_gate_zsum, cudaFuncAttributeMaxDynamicSharedMemorySize, 65536);
    k_gate_zsum<<<592, 256, 65536>>>(zs, Wb, bb, N);

    dim3 g2((N + 63) / 64, DDIM / 64);
    k_maxphi<<<g2, 256>>>(zs, Wmax, bmax, Wphi, bphi, N);
    k_combine<<<g2, 256>>>(Wc, bc, N);

    k_ln<<<(N + 7) / 8, 256>>>(gamma, beta, out, N);
}

// round 5
// speedup vs baseline: 1.5757x; 1.5755x over previous
#include <cuda_runtime.h>
#include <math.h>

#define MREL 8
#define DDIM 256
#define MAXN 51200

typedef unsigned int u32;

// ---------------- scratch (no cudaMalloc allowed) ----------------
__device__ float g_zsum[(size_t)MAXN * DDIM];
__device__ float g_zmax[(size_t)MAXN * DDIM];
__device__ float g_zagr[(size_t)MAXN * DDIM];
__device__ float g_zpre[(size_t)MAXN * DDIM];
__device__ float g_wT[16 * 256 * 256];   // [m*2+mat][e][k]  K-major
__device__ float g_wcT[256 * 768];       // [e][k]           K-major

__device__ __forceinline__ u32 f2tf(float x) {  // round-to-nearest tf32
    u32 r; asm("cvt.rna.tf32.f32 %0, %1;" : "=r"(r) : "f"(x)); return r;
}
__device__ __forceinline__ float tfbits(float x) { return __uint_as_float(f2tf(x)); }
__device__ __forceinline__ u32 fasu(float x) { return __float_as_uint(x); }

// mma.sync m16n8k8 tf32 (portable, sm_80+; HMMA on Blackwell)
__device__ __forceinline__ void mma8(float* d, const u32* a, const u32* b) {
    asm volatile(
        "mma.sync.aligned.m16n8k8.row.col.f32.tf32.tf32.f32 "
        "{%0,%1,%2,%3}, {%4,%5,%6,%7}, {%8,%9}, {%0,%1,%2,%3};"
        : "+f"(d[0]), "+f"(d[1]), "+f"(d[2]), "+f"(d[3])
        : "r"(a[0]), "r"(a[1]), "r"(a[2]), "r"(a[3]), "r"(b[0]), "r"(b[1]));
}

// ============================================================================
// Weight transposes: Wmax/Wphi [m][k][e] -> g_wT[m*2+mat][e][k]; Wc -> g_wcT
// ============================================================================
__global__ void k_wtrans(const float* __restrict__ Wmax, const float* __restrict__ Wphi) {
    __shared__ float t[32][33];
    int z = blockIdx.z;
    const float* src = ((z & 1) ? Wphi : Wmax) + (size_t)(z >> 1) * 65536;
    float* dst = g_wT + (size_t)z * 65536;
    int e0 = blockIdx.x * 32, k0 = blockIdx.y * 32;
    int tx = threadIdx.x & 31, ty = threadIdx.x >> 5;
#pragma unroll
    for (int i = 0; i < 4; i++) t[ty + i * 8][tx] = src[(size_t)(k0 + ty + i * 8) * 256 + e0 + tx];
    __syncthreads();
#pragma unroll
    for (int i = 0; i < 4; i++)
        dst[(size_t)(e0 + ty + i * 8) * 256 + k0 + tx] = t[tx][ty + i * 8];
}
__global__ void k_wctrans(const float* __restrict__ Wc) {
    __shared__ float t[32][33];
    int k0 = blockIdx.x * 32, e0 = blockIdx.y * 32;
    int tx = threadIdx.x & 31, ty = threadIdx.x >> 5;
#pragma unroll
    for (int i = 0; i < 4; i++) t[ty + i * 8][tx] = Wc[(size_t)(k0 + ty + i * 8) * 256 + e0 + tx];
    __syncthreads();
#pragma unroll
    for (int i = 0; i < 4; i++)
        g_wcT[(size_t)(e0 + ty + i * 8) * 768 + k0 + tx] = t[tx][ty + i * 8];
}

// ============================================================================
// Kernel 1: gate softmax + z_sum. One warp per node. Lane owns d = lane+32i.
// Wb rows padded to 9 words -> bank (9*row+j)%32, conflict-free (9 coprime 32).
// ============================================================================
__global__ void k_gate_zsum(const float* __restrict__ zs, const float* __restrict__ Wb,
                            const float* __restrict__ bb, int N) {
    extern __shared__ float swb[];  // 2048 * 9 floats
    int tid = threadIdx.x;
    for (int e = tid; e < 2048 * 8; e += blockDim.x)
        swb[(e >> 3) * 9 + (e & 7)] = Wb[e];
    __syncthreads();

    int lane = tid & 31, wid = tid >> 5;
    int wpb = blockDim.x >> 5, stride = wpb * gridDim.x;
    float bbv[8];
#pragma unroll
    for (int j = 0; j < 8; j++) bbv[j] = bb[j];

    for (int n = blockIdx.x * wpb + wid; n < N; n += stride) {
        float vals[MREL][8];
#pragma unroll
        for (int m = 0; m < MREL; m++) {
            const float* p = zs + ((size_t)m * N + n) * DDIM + lane;
#pragma unroll
            for (int i = 0; i < 8; i++) vals[m][i] = p[32 * i];
        }
        float lg[8] = {0.f,0.f,0.f,0.f,0.f,0.f,0.f,0.f};
#pragma unroll
        for (int m = 0; m < MREL; m++) {
#pragma unroll
            for (int i = 0; i < 8; i++) {
                const float* w = swb + (size_t)(m * DDIM + lane + 32 * i) * 9;
                float v = vals[m][i];
#pragma unroll
                for (int j = 0; j < 8; j++) lg[j] = fmaf(v, w[j], lg[j]);
            }
        }
#pragma unroll
        for (int off = 16; off > 0; off >>= 1) {
#pragma unroll
            for (int j = 0; j < 8; j++) lg[j] += __shfl_xor_sync(0xffffffffu, lg[j], off);
        }
        float mx = -1e30f;
#pragma unroll
        for (int j = 0; j < 8; j++) { lg[j] += bbv[j]; mx = fmaxf(mx, lg[j]); }
        float g[8], se = 0.f;
#pragma unroll
        for (int j = 0; j < 8; j++) { g[j] = expf(lg[j] - mx); se += g[j]; }
        float inv = 1.f / se;
        float* q = g_zsum + (size_t)n * DDIM + lane;
#pragma unroll
        for (int i = 0; i < 8; i++) {
            float a = 0.f;
#pragma unroll
            for (int m = 0; m < MREL; m++) a = fmaf(g[m], vals[m][i], a);
            q[32 * i] = a * inv;
        }
    }
}

// ============================================================================
// Kernel 2: dual-GEMM via mma.sync tf32 + fold.
// CTA tile: 64 nodes x 128 cols (cols 0-63 = Wmax@e0.., 64-127 = Wphi@e0..).
// 8 warps: warpM = wid&1 (2 x 32 rows), warpN = wid>>1 (4 x 32 cols).
// K staged in 32-wide chunks, double-buffered, stride-36 padding.
// ============================================================================
__global__ void __launch_bounds__(256) k_maxphi_mma(
        const float* __restrict__ zs,
        const float* __restrict__ bmax, const float* __restrict__ bphi, int N) {
    extern __shared__ float sh[];
    float* sbm = sh;            // [8][64]
    float* sbp = sh + 512;      // [8][64]
    float* sA  = sh + 1024;     // [2][64][36]
    float* sB  = sh + 1024 + 2 * 2304;  // [2][128][36]

    int tid = threadIdx.x, wid = tid >> 5, lane = tid & 31;
    int g = lane >> 2, t4 = lane & 3;
    int warpM = wid & 1, warpN = wid >> 1;
    int n0 = blockIdx.x * 64, e0 = blockIdx.y * 64;
    bool isProj = (warpN < 2);

    for (int i = tid; i < MREL * 64; i += 256) {
        int m = i >> 6, c = i & 63;
        sbm[i] = bmax[m * DDIM + e0 + c];
        sbp[i] = bphi[m * DDIM + e0 + c];
    }
    __syncthreads();

    // fold state: st1 = cmax (proj) or s1 (phi); st2 = s2 (phi only)
    float st1[32], st2[32];
    float init1 = isProj ? -3.0e38f : 0.f;
#pragma unroll
    for (int i = 0; i < 32; i++) { st1[i] = init1; st2[i] = 0.f; }

    for (int m = 0; m < MREL; m++) {
        const float* za = zs + (size_t)m * N * DDIM;
        const float* wm = g_wT + (size_t)(m * 2 + 0) * 65536;
        const float* wp = g_wT + (size_t)(m * 2 + 1) * 65536;

        float d[2][4][4];
#pragma unroll
        for (int mm = 0; mm < 2; mm++)
#pragma unroll
            for (int nn = 0; nn < 4; nn++)
#pragma unroll
                for (int i = 0; i < 4; i++) d[mm][nn][i] = 0.f;

        // stage chunk 0
        {
            int k0 = 0;
#pragma unroll
            for (int j = 0; j < 2; j++) {
                int f4 = tid + j * 256;            // 0..511
                int row = f4 >> 3, kq = f4 & 7;
                int nr = n0 + row; if (nr >= N) nr = N - 1;
                float4 v = *(const float4*)(za + (size_t)nr * DDIM + k0 + kq * 4);
                float* dst = sA + row * 36 + kq * 4;
                dst[0] = tfbits(v.x); dst[1] = tfbits(v.y);
                dst[2] = tfbits(v.z); dst[3] = tfbits(v.w);
            }
#pragma unroll
            for (int j = 0; j < 4; j++) {
                int f4 = tid + j * 256;            // 0..1023
                int row = f4 >> 3, kq = f4 & 7;
                const float* src = (row < 64 ? wm + (size_t)(e0 + row) * DDIM
                                             : wp + (size_t)(e0 + row - 64) * DDIM) + k0 + kq * 4;
                float4 v = *(const float4*)src;
                float* dst = sB + row * 36 + kq * 4;
                dst[0] = tfbits(v.x); dst[1] = tfbits(v.y);
                dst[2] = tfbits(v.z); dst[3] = tfbits(v.w);
            }
        }

        for (int c = 0; c < 8; c++) {
            __syncthreads();
            int buf = c & 1;
            if (c < 7) {  // stage next chunk into other buffer
                int k0 = (c + 1) * 32, nb = buf ^ 1;
                float* dA = sA + nb * 2304;
                float* dB = sB + nb * 4608;
#pragma unroll
                for (int j = 0; j < 2; j++) {
                    int f4 = tid + j * 256;
                    int row = f4 >> 3, kq = f4 & 7;
                    int nr = n0 + row; if (nr >= N) nr = N - 1;
                    float4 v = *(const float4*)(za + (size_t)nr * DDIM + k0 + kq * 4);
                    float* dst = dA + row * 36 + kq * 4;
                    dst[0] = tfbits(v.x); dst[1] = tfbits(v.y);
                    dst[2] = tfbits(v.z); dst[3] = tfbits(v.w);
                }
#pragma unroll
                for (int j = 0; j < 4; j++) {
                    int f4 = tid + j * 256;
                    int row = f4 >> 3, kq = f4 & 7;
                    const float* src = (row < 64 ? wm + (size_t)(e0 + row) * DDIM
                                                 : wp + (size_t)(e0 + row - 64) * DDIM) + k0 + kq * 4;
                    float4 v = *(const float4*)src;
                    float* dst = dB + row * 36 + kq * 4;
                    dst[0] = tfbits(v.x); dst[1] = tfbits(v.y);
                    dst[2] = tfbits(v.z); dst[3] = tfbits(v.w);
                }
            }
            const float* A = sA + buf * 2304 + (warpM * 32 + g) * 36;
            const float* B = sB + buf * 4608 + (warpN * 32 + g) * 36;
#pragma unroll
            for (int ks = 0; ks < 4; ks++) {
                int kb = ks * 8 + t4;
                u32 a[2][4], b[4][2];
#pragma unroll
                for (int mm = 0; mm < 2; mm++) {
                    const float* ar = A + mm * 16 * 36 + kb;
                    a[mm][0] = fasu(ar[0]);
                    a[mm][1] = fasu(ar[8 * 36]);
                    a[mm][2] = fasu(ar[4]);
                    a[mm][3] = fasu(ar[8 * 36 + 4]);
                }
#pragma unroll
                for (int nn = 0; nn < 4; nn++) {
                    const float* br = B + nn * 8 * 36 + kb;
                    b[nn][0] = fasu(br[0]);
                    b[nn][1] = fasu(br[4]);
                }
#pragma unroll
                for (int mm = 0; mm < 2; mm++)
#pragma unroll
                    for (int nn = 0; nn < 4; nn++) mma8(d[mm][nn], a[mm], b[nn]);
            }
        }
        __syncthreads();

        // fold this relation
        if (isProj) {
#pragma unroll
            for (int nn = 0; nn < 4; nn++) {
                float b0 = sbm[m * 64 + warpN * 32 + nn * 8 + t4 * 2];
                float b1 = sbm[m * 64 + warpN * 32 + nn * 8 + t4 * 2 + 1];
#pragma unroll
                for (int mm = 0; mm < 2; mm++) {
                    int ix = mm * 16 + nn * 4;
                    st1[ix + 0] = fmaxf(st1[ix + 0], d[mm][nn][0] + b0);
                    st1[ix + 1] = fmaxf(st1[ix + 1], d[mm][nn][1] + b1);
                    st1[ix + 2] = fmaxf(st1[ix + 2], d[mm][nn][2] + b0);
                    st1[ix + 3] = fmaxf(st1[ix + 3], d[mm][nn][3] + b1);
                }
            }
        } else {
#pragma unroll
            for (int nn = 0; nn < 4; nn++) {
                float b0 = sbp[m * 64 + (warpN - 2) * 32 + nn * 8 + t4 * 2];
                float b1 = sbp[m * 64 + (warpN - 2) * 32 + nn * 8 + t4 * 2 + 1];
#pragma unroll
                for (int mm = 0; mm < 2; mm++) {
                    int ix = mm * 16 + nn * 4;
                    float v0 = d[mm][nn][0] + b0, v1 = d[mm][nn][1] + b1;
                    float v2 = d[mm][nn][2] + b0, v3 = d[mm][nn][3] + b1;
                    st1[ix + 0] += v0; st2[ix + 0] = fmaf(v0, v0, st2[ix + 0]);
                    st1[ix + 1] += v1; st2[ix + 1] = fmaf(v1, v1, st2[ix + 1]);
                    st1[ix + 2] += v2; st2[ix + 2] = fmaf(v2, v2, st2[ix + 2]);
                    st1[ix + 3] += v3; st2[ix + 3] = fmaf(v3, v3, st2[ix + 3]);
                }
            }
        }
    }

    // write out
#pragma unroll
    for (int mm = 0; mm < 2; mm++) {
#pragma unroll
        for (int h = 0; h < 2; h++) {
            int n = n0 + warpM * 32 + mm * 16 + g + h * 8;
            if (n >= N) continue;
#pragma unroll
            for (int nn = 0; nn < 4; nn++) {
                int ix = mm * 16 + nn * 4 + h * 2;
                if (isProj) {
                    int e = e0 + warpN * 32 + nn * 8 + t4 * 2;
                    *(float2*)(g_zmax + (size_t)n * DDIM + e) =
                        make_float2(st1[ix], st1[ix + 1]);
                } else {
                    int e = e0 + (warpN - 2) * 32 + nn * 8 + t4 * 2;
                    float a0 = 0.5f * (st1[ix] * st1[ix] - st2[ix]);
                    float a1 = 0.5f * (st1[ix + 1] * st1[ix + 1] - st2[ix + 1]);
                    *(float2*)(g_zagr + (size_t)n * DDIM + e) = make_float2(a0, a1);
                }
            }
        }
    }
}

// ============================================================================
// Kernel 3: combine GEMM (K=768) via mma.sync tf32 -> g_zpre.
// CTA tile 128 nodes x 64 cols; 8 warps: warpM = wid&3, warpN = wid>>2.
// ============================================================================
__global__ void __launch_bounds__(256) k_combine_mma(
        const float* __restrict__ bc, int N) {
    extern __shared__ float sh[];
    float* sA = sh;                 // [2][128][36]
    float* sB = sh + 2 * 4608;      // [2][64][36]

    int tid = threadIdx.x, wid = tid >> 5, lane = tid & 31;
    int g = lane >> 2, t4 = lane & 3;
    int warpM = wid & 3, warpN = wid >> 2;
    int n0 = blockIdx.x * 128, e0 = blockIdx.y * 64;

    float d[2][4][4];
#pragma unroll
    for (int mm = 0; mm < 2; mm++)
#pragma unroll
        for (int nn = 0; nn < 4; nn++)
#pragma unroll
            for (int i = 0; i < 4; i++) d[mm][nn][i] = 0.f;

    // stage chunk 0
    {
        const float* src = g_zsum;
#pragma unroll
        for (int j = 0; j < 4; j++) {
            int f4 = tid + j * 256;          // 0..1023 -> A 128x32
            int row = f4 >> 3, kq = f4 & 7;
            int nr = n0 + row; if (nr >= N) nr = N - 1;
            float4 v = *(const float4*)(src + (size_t)nr * DDIM + kq * 4);
            float* dst = sA + row * 36 + kq * 4;
            dst[0] = tfbits(v.x); dst[1] = tfbits(v.y);
            dst[2] = tfbits(v.z); dst[3] = tfbits(v.w);
        }
#pragma unroll
        for (int j = 0; j < 2; j++) {
            int f4 = tid + j * 256;          // 0..511 -> B 64x32
            int row = f4 >> 3, kq = f4 & 7;
            float4 v = *(const float4*)(g_wcT + (size_t)(e0 + row) * 768 + kq * 4);
            float* dst = sB + row * 36 + kq * 4;
            dst[0] = tfbits(v.x); dst[1] = tfbits(v.y);
            dst[2] = tfbits(v.z); dst[3] = tfbits(v.w);
        }
    }

    for (int c = 0; c < 24; c++) {
        __syncthreads();
        int buf = c & 1;
        if (c < 23) {
            int k0 = (c + 1) * 32, nb = buf ^ 1;
            const float* src = (k0 < 256) ? g_zsum : (k0 < 512) ? g_zmax : g_zagr;
            int kc = k0 & 255;
            float* dA = sA + nb * 4608;
            float* dB = sB + nb * 2304;
#pragma unroll
            for (int j = 0; j < 4; j++) {
                int f4 = tid + j * 256;
                int row = f4 >> 3, kq = f4 & 7;
                int nr = n0 + row; if (nr >= N) nr = N - 1;
                float4 v = *(const float4*)(src + (size_t)nr * DDIM + kc + kq * 4);
                float* dst = dA + row * 36 + kq * 4;
                dst[0] = tfbits(v.x); dst[1] = tfbits(v.y);
                dst[2] = tfbits(v.z); dst[3] = tfbits(v.w);
            }
#pragma unroll
            for (int j = 0; j < 2; j++) {
                int f4 = tid + j * 256;
                int row = f4 >> 3, kq = f4 & 7;
                float4 v = *(const float4*)(g_wcT + (size_t)(e0 + row) * 768 + k0 + kq * 4);
                float* dst = dB + row * 36 + kq * 4;
                dst[0] = tfbits(v.x); dst[1] = tfbits(v.y);
                dst[2] = tfbits(v.z); dst[3] = tfbits(v.w);
            }
        }
        const float* A = sA + buf * 4608 + (warpM * 32 + g) * 36;
        const float* B = sB + buf * 2304 + (warpN * 32 + g) * 36;
#pragma unroll
        for (int ks = 0; ks < 4; ks++) {
            int kb = ks * 8 + t4;
            u32 a[2][4], b[4][2];
#pragma unroll
            for (int mm = 0; mm < 2; mm++) {
                const float* ar = A + mm * 16 * 36 + kb;
                a[mm][0] = fasu(ar[0]);
                a[mm][1] = fasu(ar[8 * 36]);
                a[mm][2] = fasu(ar[4]);
                a[mm][3] = fasu(ar[8 * 36 + 4]);
            }
#pragma unroll
            for (int nn = 0; nn < 4; nn++) {
                const float* br = B + nn * 8 * 36 + kb;
                b[nn][0] = fasu(br[0]);
                b[nn][1] = fasu(br[4]);
            }
#pragma unroll
            for (int mm = 0; mm < 2; mm++)
#pragma unroll
                for (int nn = 0; nn < 4; nn++) mma8(d[mm][nn], a[mm], b[nn]);
        }
    }

#pragma unroll
    for (int mm = 0; mm < 2; mm++) {
#pragma unroll
        for (int h = 0; h < 2; h++) {
            int n = n0 + warpM * 32 + mm * 16 + g + h * 8;
            if (n >= N) continue;
#pragma unroll
            for (int nn = 0; nn < 4; nn++) {
                int e = e0 + warpN * 32 + nn * 8 + t4 * 2;
                float b0 = __ldg(bc + e), b1 = __ldg(bc + e + 1);
                *(float2*)(g_zpre + (size_t)n * DDIM + e) =
                    make_float2(d[mm][nn][h * 2] + b0, d[mm][nn][h * 2 + 1] + b1);
            }
        }
    }
}

// ============================================================================
// Kernel 4: LayerNorm. One warp per node.
// ============================================================================
__global__ void k_ln(const float* __restrict__ gamma, const float* __restrict__ beta,
                     float* __restrict__ out, int N) {
    int tid = threadIdx.x;
    int lane = tid & 31, wid = tid >> 5;
    int n = blockIdx.x * (blockDim.x >> 5) + wid;
    if (n >= N) return;

    const float* p = g_zpre + (size_t)n * DDIM + lane * 8;
    float4 v0 = *(const float4*)p;
    float4 v1 = *(const float4*)(p + 4);
    float v[8] = {v0.x, v0.y, v0.z, v0.w, v1.x, v1.y, v1.z, v1.w};
    float s = 0.f, q = 0.f;
#pragma unroll
    for (int dd = 0; dd < 8; dd++) { s += v[dd]; q = fmaf(v[dd], v[dd], q); }
#pragma unroll
    for (int off = 16; off > 0; off >>= 1) {
        s += __shfl_xor_sync(0xffffffffu, s, off);
        q += __shfl_xor_sync(0xffffffffu, q, off);
    }
    float mean = s * (1.f / 256.f);
    float var = q * (1.f / 256.f) - mean * mean;
    float inv = rsqrtf(var + 1e-5f);

    const float* gp = gamma + lane * 8;
    const float* bp = beta + lane * 8;
    float4 g0 = *(const float4*)gp, g1 = *(const float4*)(gp + 4);
    float4 b0 = *(const float4*)bp, b1 = *(const float4*)(bp + 4);
    float gg[8] = {g0.x, g0.y, g0.z, g0.w, g1.x, g1.y, g1.z, g1.w};
    float bbv[8] = {b0.x, b0.y, b0.z, b0.w, b1.x, b1.y, b1.z, b1.w};
    float o[8];
#pragma unroll
    for (int dd = 0; dd < 8; dd++) o[dd] = fmaf((v[dd] - mean) * inv, gg[dd], bbv[dd]);

    float* qo = out + (size_t)n * DDIM + lane * 8;
    *(float4*)qo       = make_float4(o[0], o[1], o[2], o[3]);
    *(float4*)(qo + 4) = make_float4(o[4], o[5], o[6], o[7]);
}

// ============================================================================
extern "C" void kernel_launch(void* const* d_in, const int* in_sizes, int n_in,
                              void* d_out, int out_size) {
    const float* zs    = (const float*)d_in[0];
    const float* Wb    = (const float*)d_in[1];
    const float* bb    = (const float*)d_in[2];
    const float* Wmax  = (const float*)d_in[3];
    const float* bmax  = (const float*)d_in[4];
    const float* Wphi  = (const float*)d_in[5];
    const float* bphi  = (const float*)d_in[6];
    const float* Wc    = (const float*)d_in[7];
    const float* bc    = (const float*)d_in[8];
    const float* gamma = (const float*)d_in[9];
    const float* beta  = (const float*)d_in[10];
    float* out = (float*)d_out;

    int N = in_sizes[0] / (MREL * DDIM);

    cudaFuncSetAttribute(k_gate_zsum, cudaFuncAttributeMaxDynamicSharedMemorySize, 73728);
    cudaFuncSetAttribute(k_maxphi_mma, cudaFuncAttributeMaxDynamicSharedMemorySize, 59392);
    cudaFuncSetAttribute(k_combine_mma, cudaFuncAttributeMaxDynamicSharedMemorySize, 55296);

    k_wtrans<<<dim3(8, 8, 16), 256>>>(Wmax, Wphi);
    k_wctrans<<<dim3(24, 8), 256>>>(Wc);

    k_gate_zsum<<<592, 256, 73728>>>(zs, Wb, bb, N);

    dim3 gm((N + 63) / 64, 4);
    k_maxphi_mma<<<gm, 256, 59392>>>(zs, bmax, bphi, N);

    dim3 gc((N + 127) / 128, 4);
    k_combine_mma<<<gc, 256, 55296>>>(bc, N);

    k_ln<<<(N + 7) / 8, 256>>>(gamma, beta, out, N);
}

// round 6
// speedup vs baseline: 2.3001x; 1.4598x over previous
#include <cuda_runtime.h>
#include <math.h>

#define MREL 8
#define DDIM 256
#define MAXN 51200

typedef unsigned int u32;

// ---------------- scratch (no cudaMalloc allowed) ----------------
__device__ float g_zs[(size_t)MREL * MAXN * DDIM];   // tf32-rounded copy of zs
__device__ float g_zsum[(size_t)MAXN * DDIM];        // tf32-rounded
__device__ float g_zmax[(size_t)MAXN * DDIM];        // tf32-rounded
__device__ float g_zagr[(size_t)MAXN * DDIM];        // tf32-rounded
__device__ float g_zpre[(size_t)MAXN * DDIM];        // fp32
__device__ float g_wT[16 * 256 * 256];               // [m*2+mat][e][k] K-major, tf32
__device__ float g_wcT[256 * 768];                   // [e][k] K-major, tf32

__device__ __forceinline__ u32 f2tf(float x) {
    u32 r; asm("cvt.rna.tf32.f32 %0, %1;" : "=r"(r) : "f"(x)); return r;
}
__device__ __forceinline__ float tfbits(float x) { return __uint_as_float(f2tf(x)); }
__device__ __forceinline__ u32 fasu(float x) { return __float_as_uint(x); }

__device__ __forceinline__ void mma8(float* d, const u32* a, const u32* b) {
    asm volatile(
        "mma.sync.aligned.m16n8k8.row.col.f32.tf32.tf32.f32 "
        "{%0,%1,%2,%3}, {%4,%5,%6,%7}, {%8,%9}, {%0,%1,%2,%3};"
        : "+f"(d[0]), "+f"(d[1]), "+f"(d[2]), "+f"(d[3])
        : "r"(a[0]), "r"(a[1]), "r"(a[2]), "r"(a[3]), "r"(b[0]), "r"(b[1]));
}
__device__ __forceinline__ void cpa16(u32 dst, const void* src) {
    asm volatile("cp.async.cg.shared.global [%0], [%1], 16;" :: "r"(dst), "l"(src));
}
#define CP_COMMIT() asm volatile("cp.async.commit_group;")
#define CP_WAIT1()  asm volatile("cp.async.wait_group 1;")

// ============================================================================
// Weight transposes (tf32-rounded outputs)
// ============================================================================
__global__ void k_wtrans(const float* __restrict__ Wmax, const float* __restrict__ Wphi) {
    __shared__ float t[32][33];
    int z = blockIdx.z;
    const float* src = ((z & 1) ? Wphi : Wmax) + (size_t)(z >> 1) * 65536;
    float* dst = g_wT + (size_t)z * 65536;
    int e0 = blockIdx.x * 32, k0 = blockIdx.y * 32;
    int tx = threadIdx.x & 31, ty = threadIdx.x >> 5;
#pragma unroll
    for (int i = 0; i < 4; i++) t[ty + i * 8][tx] = src[(size_t)(k0 + ty + i * 8) * 256 + e0 + tx];
    __syncthreads();
#pragma unroll
    for (int i = 0; i < 4; i++)
        dst[(size_t)(e0 + ty + i * 8) * 256 + k0 + tx] = tfbits(t[tx][ty + i * 8]);
}
__global__ void k_wctrans(const float* __restrict__ Wc) {
    __shared__ float t[32][33];
    int k0 = blockIdx.x * 32, e0 = blockIdx.y * 32;
    int tx = threadIdx.x & 31, ty = threadIdx.x >> 5;
#pragma unroll
    for (int i = 0; i < 4; i++) t[ty + i * 8][tx] = Wc[(size_t)(k0 + ty + i * 8) * 256 + e0 + tx];
    __syncthreads();
#pragma unroll
    for (int i = 0; i < 4; i++)
        g_wcT[(size_t)(e0 + ty + i * 8) * 768 + k0 + tx] = tfbits(t[tx][ty + i * 8]);
}

// ============================================================================
// Kernel 1: gate softmax + z_sum; also writes tf32-rounded zs copy (g_zs) and
// tf32-rounded z_sum (g_zsum, consumed only by the combine GEMM).
// ============================================================================
__global__ void k_gate_zsum(const float* __restrict__ zs, const float* __restrict__ Wb,
                            const float* __restrict__ bb, int N) {
    extern __shared__ float swb[];  // 2048 * 9
    int tid = threadIdx.x;
    for (int e = tid; e < 2048 * 8; e += blockDim.x)
        swb[(e >> 3) * 9 + (e & 7)] = Wb[e];
    __syncthreads();

    int lane = tid & 31, wid = tid >> 5;
    int wpb = blockDim.x >> 5, stride = wpb * gridDim.x;
    float bbv[8];
#pragma unroll
    for (int j = 0; j < 8; j++) bbv[j] = bb[j];

    for (int n = blockIdx.x * wpb + wid; n < N; n += stride) {
        float vals[MREL][8];
#pragma unroll
        for (int m = 0; m < MREL; m++) {
            const float* p = zs + ((size_t)m * N + n) * DDIM + lane;
            float* zr = g_zs + ((size_t)m * N + n) * DDIM + lane;
#pragma unroll
            for (int i = 0; i < 8; i++) {
                vals[m][i] = p[32 * i];
                zr[32 * i] = tfbits(vals[m][i]);
            }
        }
        float lg[8] = {0.f,0.f,0.f,0.f,0.f,0.f,0.f,0.f};
#pragma unroll
        for (int m = 0; m < MREL; m++) {
#pragma unroll
            for (int i = 0; i < 8; i++) {
                const float* w = swb + (size_t)(m * DDIM + lane + 32 * i) * 9;
                float v = vals[m][i];
#pragma unroll
                for (int j = 0; j < 8; j++) lg[j] = fmaf(v, w[j], lg[j]);
            }
        }
#pragma unroll
        for (int off = 16; off > 0; off >>= 1) {
#pragma unroll
            for (int j = 0; j < 8; j++) lg[j] += __shfl_xor_sync(0xffffffffu, lg[j], off);
        }
        float mx = -1e30f;
#pragma unroll
        for (int j = 0; j < 8; j++) { lg[j] += bbv[j]; mx = fmaxf(mx, lg[j]); }
        float g[8], se = 0.f;
#pragma unroll
        for (int j = 0; j < 8; j++) { g[j] = expf(lg[j] - mx); se += g[j]; }
        float inv = 1.f / se;
        float* q = g_zsum + (size_t)n * DDIM + lane;
#pragma unroll
        for (int i = 0; i < 8; i++) {
            float a = 0.f;
#pragma unroll
            for (int m = 0; m < MREL; m++) a = fmaf(g[m], vals[m][i], a);
            q[32 * i] = tfbits(a * inv);
        }
    }
}

// ============================================================================
// Kernel 2: dual-GEMM (mma.sync tf32) + fold, cp.async 3-stage pipeline.
// CTA tile: 64 nodes x 64 out cols x (proj+phi). 8 warps = 2M x 4N.
// 64 iterations = 8 relations x 8 K-chunks of 32.
// smem: biases 4096B | A stages 3 x 9216B | B stages 3 x 18432B  (87040B)
// ============================================================================
__global__ void __launch_bounds__(256, 2) k_maxphi_mma(
        const float* __restrict__ bmax, const float* __restrict__ bphi, int N) {
    extern __shared__ float sh[];
    u32 shb = (u32)__cvta_generic_to_shared(sh);
    float* sbm = sh;                    // [8][64]
    float* sbp = sh + 512;              // [8][64]
    float* sAf = sh + 1024;             // 3 x [64][36]
    float* sBf = sh + 1024 + 3 * 2304;  // 3 x [128][36]
    const u32 A0 = shb + 4096, B0 = shb + 4096 + 3 * 9216;

    int tid = threadIdx.x, wid = tid >> 5, lane = tid & 31;
    int g = lane >> 2, t4 = lane & 3;
    int warpM = wid & 1, warpN = wid >> 1;
    int e0 = blockIdx.x * 64, n0 = blockIdx.y * 64;
    bool isProj = (warpN < 2);

    for (int i = tid; i < MREL * 64; i += 256) {
        int m = i >> 6, c = i & 63;
        sbm[i] = bmax[m * DDIM + e0 + c];
        sbp[i] = bphi[m * DDIM + e0 + c];
    }

    // staging lambda (all 256 threads)
    auto stage = [&](int it) {
        int m = it >> 3, k0 = (it & 7) * 32, s = it % 3;
        const float* za = g_zs + (size_t)m * N * DDIM;
        const float* wb = g_wT + (size_t)m * 2 * 65536;
        u32 sa = A0 + s * 9216, sb = B0 + s * 18432;
#pragma unroll
        for (int j = 0; j < 2; j++) {
            int f = tid + j * 256;             // A: 512 16B chunks
            int row = f >> 3, kq = f & 7;
            int nr = n0 + row; if (nr >= N) nr = N - 1;
            cpa16(sa + row * 144 + kq * 16, za + (size_t)nr * DDIM + k0 + kq * 4);
        }
#pragma unroll
        for (int j = 0; j < 4; j++) {
            int f = tid + j * 256;             // B: 1024 16B chunks
            int row = f >> 3, kq = f & 7;
            const float* src = wb + (row >= 64 ? 65536 : 0)
                               + (size_t)(e0 + (row & 63)) * 256 + k0 + kq * 4;
            cpa16(sb + row * 144 + kq * 16, src);
        }
    };

    stage(0); CP_COMMIT();
    stage(1); CP_COMMIT();

    float st1[32], st2[32];
    float init1 = isProj ? -3.0e38f : 0.f;
#pragma unroll
    for (int i = 0; i < 32; i++) { st1[i] = init1; st2[i] = 0.f; }

    float d[2][4][4];

    for (int it = 0; it < 64; it++) {
        int m = it >> 3, chunk = it & 7, s = it % 3;
        if (chunk == 0) {
#pragma unroll
            for (int mm = 0; mm < 2; mm++)
#pragma unroll
                for (int nn = 0; nn < 4; nn++)
#pragma unroll
                    for (int i = 0; i < 4; i++) d[mm][nn][i] = 0.f;
        }
        CP_WAIT1();
        __syncthreads();
        if (it + 2 < 64) { stage(it + 2); CP_COMMIT(); }

        const float* A = sAf + s * 2304 + (warpM * 32 + g) * 36;
        const float* B = sBf + s * 4608 + (warpN * 32 + g) * 36;
#pragma unroll
        for (int ks = 0; ks < 4; ks++) {
            int kb = ks * 8 + t4;
            u32 a[2][4], b[4][2];
#pragma unroll
            for (int mm = 0; mm < 2; mm++) {
                const float* ar = A + mm * 16 * 36 + kb;
                a[mm][0] = fasu(ar[0]);
                a[mm][1] = fasu(ar[8 * 36]);
                a[mm][2] = fasu(ar[4]);
                a[mm][3] = fasu(ar[8 * 36 + 4]);
            }
#pragma unroll
            for (int nn = 0; nn < 4; nn++) {
                const float* br = B + nn * 8 * 36 + kb;
                b[nn][0] = fasu(br[0]);
                b[nn][1] = fasu(br[4]);
            }
#pragma unroll
            for (int mm = 0; mm < 2; mm++)
#pragma unroll
                for (int nn = 0; nn < 4; nn++) mma8(d[mm][nn], a[mm], b[nn]);
        }

        if (chunk == 7) {  // fold relation m (registers + constant smem biases)
            if (isProj) {
#pragma unroll
                for (int nn = 0; nn < 4; nn++) {
                    float b0 = sbm[m * 64 + warpN * 32 + nn * 8 + t4 * 2];
                    float b1 = sbm[m * 64 + warpN * 32 + nn * 8 + t4 * 2 + 1];
#pragma unroll
                    for (int mm = 0; mm < 2; mm++) {
                        int ix = mm * 16 + nn * 4;
                        st1[ix + 0] = fmaxf(st1[ix + 0], d[mm][nn][0] + b0);
                        st1[ix + 1] = fmaxf(st1[ix + 1], d[mm][nn][1] + b1);
                        st1[ix + 2] = fmaxf(st1[ix + 2], d[mm][nn][2] + b0);
                        st1[ix + 3] = fmaxf(st1[ix + 3], d[mm][nn][3] + b1);
                    }
                }
            } else {
#pragma unroll
                for (int nn = 0; nn < 4; nn++) {
                    float b0 = sbp[m * 64 + (warpN - 2) * 32 + nn * 8 + t4 * 2];
                    float b1 = sbp[m * 64 + (warpN - 2) * 32 + nn * 8 + t4 * 2 + 1];
#pragma unroll
                    for (int mm = 0; mm < 2; mm++) {
                        int ix = mm * 16 + nn * 4;
                        float v0 = d[mm][nn][0] + b0, v1 = d[mm][nn][1] + b1;
                        float v2 = d[mm][nn][2] + b0, v3 = d[mm][nn][3] + b1;
                        st1[ix + 0] += v0; st2[ix + 0] = fmaf(v0, v0, st2[ix + 0]);
                        st1[ix + 1] += v1; st2[ix + 1] = fmaf(v1, v1, st2[ix + 1]);
                        st1[ix + 2] += v2; st2[ix + 2] = fmaf(v2, v2, st2[ix + 2]);
                        st1[ix + 3] += v3; st2[ix + 3] = fmaf(v3, v3, st2[ix + 3]);
                    }
                }
            }
        }
    }

#pragma unroll
    for (int mm = 0; mm < 2; mm++) {
#pragma unroll
        for (int h = 0; h < 2; h++) {
            int n = n0 + warpM * 32 + mm * 16 + g + h * 8;
            if (n >= N) continue;
#pragma unroll
            for (int nn = 0; nn < 4; nn++) {
                int ix = mm * 16 + nn * 4 + h * 2;
                if (isProj) {
                    int e = e0 + warpN * 32 + nn * 8 + t4 * 2;
                    *(float2*)(g_zmax + (size_t)n * DDIM + e) =
                        make_float2(tfbits(st1[ix]), tfbits(st1[ix + 1]));
                } else {
                    int e = e0 + (warpN - 2) * 32 + nn * 8 + t4 * 2;
                    float a0 = 0.5f * (st1[ix] * st1[ix] - st2[ix]);
                    float a1 = 0.5f * (st1[ix + 1] * st1[ix + 1] - st2[ix + 1]);
                    *(float2*)(g_zagr + (size_t)n * DDIM + e) =
                        make_float2(tfbits(a0), tfbits(a1));
                }
            }
        }
    }
}

// ============================================================================
// Kernel 3: combine GEMM (K=768) cp.async 3-stage -> g_zpre (fp32).
// CTA 128 nodes x 64 cols; 8 warps = 4M x 2N.
// smem: A stages 3 x 18432B | B stages 3 x 9216B  (82944B)
// ============================================================================
__global__ void __launch_bounds__(256, 2) k_combine_mma(
        const float* __restrict__ bc, int N) {
    extern __shared__ float sh[];
    u32 shb = (u32)__cvta_generic_to_shared(sh);
    float* sAf = sh;                 // 3 x [128][36]
    float* sBf = sh + 3 * 4608;      // 3 x [64][36]
    const u32 A0 = shb, B0 = shb + 3 * 18432;

    int tid = threadIdx.x, wid = tid >> 5, lane = tid & 31;
    int g = lane >> 2, t4 = lane & 3;
    int warpM = wid & 3, warpN = wid >> 2;
    int e0 = blockIdx.x * 64, n0 = blockIdx.y * 128;

    auto stage = [&](int c) {
        int k0 = c * 32, s = c % 3;
        const float* src = (k0 < 256) ? g_zsum : (k0 < 512) ? g_zmax : g_zagr;
        int kc = k0 & 255;
        u32 sa = A0 + s * 18432, sb = B0 + s * 9216;
#pragma unroll
        for (int j = 0; j < 4; j++) {
            int f = tid + j * 256;           // A: 1024 chunks
            int row = f >> 3, kq = f & 7;
            int nr = n0 + row; if (nr >= N) nr = N - 1;
            cpa16(sa + row * 144 + kq * 16, src + (size_t)nr * DDIM + kc + kq * 4);
        }
#pragma unroll
        for (int j = 0; j < 2; j++) {
            int f = tid + j * 256;           // B: 512 chunks
            int row = f >> 3, kq = f & 7;
            cpa16(sb + row * 144 + kq * 16, g_wcT + (size_t)(e0 + row) * 768 + k0 + kq * 4);
        }
    };

    stage(0); CP_COMMIT();
    stage(1); CP_COMMIT();

    float d[2][4][4];
#pragma unroll
    for (int mm = 0; mm < 2; mm++)
#pragma unroll
        for (int nn = 0; nn < 4; nn++)
#pragma unroll
            for (int i = 0; i < 4; i++) d[mm][nn][i] = 0.f;

    for (int c = 0; c < 24; c++) {
        int s = c % 3;
        CP_WAIT1();
        __syncthreads();
        if (c + 2 < 24) { stage(c + 2); CP_COMMIT(); }

        const float* A = sAf + s * 4608 + (warpM * 32 + g) * 36;
        const float* B = sBf + s * 2304 + (warpN * 32 + g) * 36;
#pragma unroll
        for (int ks = 0; ks < 4; ks++) {
            int kb = ks * 8 + t4;
            u32 a[2][4], b[4][2];
#pragma unroll
            for (int mm = 0; mm < 2; mm++) {
                const float* ar = A + mm * 16 * 36 + kb;
                a[mm][0] = fasu(ar[0]);
                a[mm][1] = fasu(ar[8 * 36]);
                a[mm][2] = fasu(ar[4]);
                a[mm][3] = fasu(ar[8 * 36 + 4]);
            }
#pragma unroll
            for (int nn = 0; nn < 4; nn++) {
                const float* br = B + nn * 8 * 36 + kb;
                b[nn][0] = fasu(br[0]);
                b[nn][1] = fasu(br[4]);
            }
#pragma unroll
            for (int mm = 0; mm < 2; mm++)
#pragma unroll
                for (int nn = 0; nn < 4; nn++) mma8(d[mm][nn], a[mm], b[nn]);
        }
    }

#pragma unroll
    for (int mm = 0; mm < 2; mm++) {
#pragma unroll
        for (int h = 0; h < 2; h++) {
            int n = n0 + warpM * 32 + mm * 16 + g + h * 8;
            if (n >= N) continue;
#pragma unroll
            for (int nn = 0; nn < 4; nn++) {
                int e = e0 + warpN * 32 + nn * 8 + t4 * 2;
                float b0 = __ldg(bc + e), b1 = __ldg(bc + e + 1);
                *(float2*)(g_zpre + (size_t)n * DDIM + e) =
                    make_float2(d[mm][nn][h * 2] + b0, d[mm][nn][h * 2 + 1] + b1);
            }
        }
    }
}

// ============================================================================
// Kernel 4: LayerNorm. One warp per node.
// ============================================================================
__global__ void k_ln(const float* __restrict__ gamma, const float* __restrict__ beta,
                     float* __restrict__ out, int N) {
    int tid = threadIdx.x;
    int lane = tid & 31, wid = tid >> 5;
    int n = blockIdx.x * (blockDim.x >> 5) + wid;
    if (n >= N) return;

    const float* p = g_zpre + (size_t)n * DDIM + lane * 8;
    float4 v0 = *(const float4*)p;
    float4 v1 = *(const float4*)(p + 4);
    float v[8] = {v0.x, v0.y, v0.z, v0.w, v1.x, v1.y, v1.z, v1.w};
    float s = 0.f, q = 0.f;
#pragma unroll
    for (int dd = 0; dd < 8; dd++) { s += v[dd]; q = fmaf(v[dd], v[dd], q); }
#pragma unroll
    for (int off = 16; off > 0; off >>= 1) {
        s += __shfl_xor_sync(0xffffffffu, s, off);
        q += __shfl_xor_sync(0xffffffffu, q, off);
    }
    float mean = s * (1.f / 256.f);
    float var = q * (1.f / 256.f) - mean * mean;
    float inv = rsqrtf(var + 1e-5f);

    const float* gp = gamma + lane * 8;
    const float* bp = beta + lane * 8;
    float4 g0 = *(const float4*)gp, g1 = *(const float4*)(gp + 4);
    float4 b0 = *(const float4*)bp, b1 = *(const float4*)(bp + 4);
    float gg[8] = {g0.x, g0.y, g0.z, g0.w, g1.x, g1.y, g1.z, g1.w};
    float bbv[8] = {b0.x, b0.y, b0.z, b0.w, b1.x, b1.y, b1.z, b1.w};
    float o[8];
#pragma unroll
    for (int dd = 0; dd < 8; dd++) o[dd] = fmaf((v[dd] - mean) * inv, gg[dd], bbv[dd]);

    float* qo = out + (size_t)n * DDIM + lane * 8;
    *(float4*)qo       = make_float4(o[0], o[1], o[2], o[3]);
    *(float4*)(qo + 4) = make_float4(o[4], o[5], o[6], o[7]);
}

// ============================================================================
extern "C" void kernel_launch(void* const* d_in, const int* in_sizes, int n_in,
                              void* d_out, int out_size) {
    const float* zs    = (const float*)d_in[0];
    const float* Wb    = (const float*)d_in[1];
    const float* bb    = (const float*)d_in[2];
    const float* Wmax  = (const float*)d_in[3];
    const float* bmax  = (const float*)d_in[4];
    const float* Wphi  = (const float*)d_in[5];
    const float* bphi  = (const float*)d_in[6];
    const float* Wc    = (const float*)d_in[7];
    const float* bc    = (const float*)d_in[8];
    const float* gamma = (const float*)d_in[9];
    const float* beta  = (const float*)d_in[10];
    float* out = (float*)d_out;

    int N = in_sizes[0] / (MREL * DDIM);

    cudaFuncSetAttribute(k_gate_zsum, cudaFuncAttributeMaxDynamicSharedMemorySize, 73728);
    cudaFuncSetAttribute(k_maxphi_mma, cudaFuncAttributeMaxDynamicSharedMemorySize, 87040);
    cudaFuncSetAttribute(k_combine_mma, cudaFuncAttributeMaxDynamicSharedMemorySize, 82944);

    k_wtrans<<<dim3(8, 8, 16), 256>>>(Wmax, Wphi);
    k_wctrans<<<dim3(24, 8), 256>>>(Wc);

    k_gate_zsum<<<592, 256, 73728>>>(zs, Wb, bb, N);

    dim3 gm(4, (N + 63) / 64);
    k_maxphi_mma<<<gm, 256, 87040>>>(bmax, bphi, N);

    dim3 gc(4, (N + 127) / 128);
    k_combine_mma<<<gc, 256, 82944>>>(bc, N);

    k_ln<<<(N + 7) / 8, 256>>>(gamma, beta, out, N);
}

// round 7
// speedup vs baseline: 2.4674x; 1.0727x over previous
#include <cuda_runtime.h>
#include <math.h>

#define MREL 8
#define DDIM 256
#define MAXN 51200

typedef unsigned int u32;

// ---------------- scratch (no cudaMalloc allowed) ----------------
__device__ float g_zsum[(size_t)MAXN * DDIM];        // fp32 (unrounded)
__device__ float g_zmax[(size_t)MAXN * DDIM];        // fp32
__device__ float g_zagr[(size_t)MAXN * DDIM];        // fp32
__device__ float g_zpre[(size_t)MAXN * DDIM];        // fp32
__device__ float g_wT[16 * 256 * 256];               // [m*2+mat][e][k] K-major, rna-tf32
__device__ float g_wcT[256 * 768];                   // [e][k] K-major, rna-tf32

__device__ __forceinline__ u32 f2tf(float x) {       // round-to-nearest tf32 (bits in fp32 container)
    u32 r; asm("cvt.rna.tf32.f32 %0, %1;" : "=r"(r) : "f"(x)); return r;
}
__device__ __forceinline__ float tfbits(float x) { return __uint_as_float(f2tf(x)); }
__device__ __forceinline__ u32 fasu(float x) { return __float_as_uint(x); }

__device__ __forceinline__ void mma8(float* d, const u32* a, const u32* b) {
    asm volatile(
        "mma.sync.aligned.m16n8k8.row.col.f32.tf32.tf32.f32 "
        "{%0,%1,%2,%3}, {%4,%5,%6,%7}, {%8,%9}, {%0,%1,%2,%3};"
        : "+f"(d[0]), "+f"(d[1]), "+f"(d[2]), "+f"(d[3])
        : "r"(a[0]), "r"(a[1]), "r"(a[2]), "r"(a[3]), "r"(b[0]), "r"(b[1]));
}
__device__ __forceinline__ void cpa16(u32 dst, const void* src) {
    asm volatile("cp.async.cg.shared.global [%0], [%1], 16;" :: "r"(dst), "l"(src));
}
#define CP_COMMIT() asm volatile("cp.async.commit_group;")
#define CP_WAIT0()  asm volatile("cp.async.wait_group 0;")

// ============================================================================
// Weight transposes (rna-tf32 outputs)
// ============================================================================
__global__ void k_wtrans(const float* __restrict__ Wmax, const float* __restrict__ Wphi) {
    __shared__ float t[32][33];
    int z = blockIdx.z;
    const float* src = ((z & 1) ? Wphi : Wmax) + (size_t)(z >> 1) * 65536;
    float* dst = g_wT + (size_t)z * 65536;
    int e0 = blockIdx.x * 32, k0 = blockIdx.y * 32;
    int tx = threadIdx.x & 31, ty = threadIdx.x >> 5;
#pragma unroll
    for (int i = 0; i < 4; i++) t[ty + i * 8][tx] = src[(size_t)(k0 + ty + i * 8) * 256 + e0 + tx];
    __syncthreads();
#pragma unroll
    for (int i = 0; i < 4; i++)
        dst[(size_t)(e0 + ty + i * 8) * 256 + k0 + tx] = tfbits(t[tx][ty + i * 8]);
}
__global__ void k_wctrans(const float* __restrict__ Wc) {
    __shared__ float t[32][33];
    int k0 = blockIdx.x * 32, e0 = blockIdx.y * 32;
    int tx = threadIdx.x & 31, ty = threadIdx.x >> 5;
#pragma unroll
    for (int i = 0; i < 4; i++) t[ty + i * 8][tx] = Wc[(size_t)(k0 + ty + i * 8) * 256 + e0 + tx];
    __syncthreads();
#pragma unroll
    for (int i = 0; i < 4; i++)
        g_wcT[(size_t)(e0 + ty + i * 8) * 768 + k0 + tx] = tfbits(t[tx][ty + i * 8]);
}

// ============================================================================
// Kernel 1: gate softmax + z_sum (fp32 out). One warp per node.
// ============================================================================
__global__ void k_gate_zsum(const float* __restrict__ zs, const float* __restrict__ Wb,
                            const float* __restrict__ bb, int N) {
    extern __shared__ float swb[];  // 2048 * 9
    int tid = threadIdx.x;
    for (int e = tid; e < 2048 * 8; e += blockDim.x)
        swb[(e >> 3) * 9 + (e & 7)] = Wb[e];
    __syncthreads();

    int lane = tid & 31, wid = tid >> 5;
    int wpb = blockDim.x >> 5, stride = wpb * gridDim.x;
    float bbv[8];
#pragma unroll
    for (int j = 0; j < 8; j++) bbv[j] = bb[j];

    for (int n = blockIdx.x * wpb + wid; n < N; n += stride) {
        float vals[MREL][8];
#pragma unroll
        for (int m = 0; m < MREL; m++) {
            const float* p = zs + ((size_t)m * N + n) * DDIM + lane;
#pragma unroll
            for (int i = 0; i < 8; i++) vals[m][i] = p[32 * i];
        }
        float lg[8] = {0.f,0.f,0.f,0.f,0.f,0.f,0.f,0.f};
#pragma unroll
        for (int m = 0; m < MREL; m++) {
#pragma unroll
            for (int i = 0; i < 8; i++) {
                const float* w = swb + (size_t)(m * DDIM + lane + 32 * i) * 9;
                float v = vals[m][i];
#pragma unroll
                for (int j = 0; j < 8; j++) lg[j] = fmaf(v, w[j], lg[j]);
            }
        }
#pragma unroll
        for (int off = 16; off > 0; off >>= 1) {
#pragma unroll
            for (int j = 0; j < 8; j++) lg[j] += __shfl_xor_sync(0xffffffffu, lg[j], off);
        }
        float mx = -1e30f;
#pragma unroll
        for (int j = 0; j < 8; j++) { lg[j] += bbv[j]; mx = fmaxf(mx, lg[j]); }
        float g[8], se = 0.f;
#pragma unroll
        for (int j = 0; j < 8; j++) { g[j] = expf(lg[j] - mx); se += g[j]; }
        float inv = 1.f / se;
        float* q = g_zsum + (size_t)n * DDIM + lane;
#pragma unroll
        for (int i = 0; i < 8; i++) {
            float a = 0.f;
#pragma unroll
            for (int m = 0; m < MREL; m++) a = fmaf(g[m], vals[m][i], a);
            q[32 * i] = a * inv;
        }
    }
}

// ============================================================================
// Kernel 2: fused dual-GEMM + fold. CTA tile 128 nodes x 64 e-cols, both
// proj and phi per warp (A-fragments amortized 2x). K-chunk 64, 2-stage
// cp.async. A = raw zs (fp32), rna at fragment load. B = g_wT (pre-rounded).
// 32 iterations = 8 relations x 4 chunks. 1 CTA/SM (smem 140KB).
// warps: warpM = wid&3 (32 rows each), warpN = wid>>2 (32 cols each).
// ============================================================================
__global__ void __launch_bounds__(256, 1) k_maxphi_mma(
        const float* __restrict__ zs,
        const float* __restrict__ bmax, const float* __restrict__ bphi, int N) {
    extern __shared__ float sh[];
    u32 shb = (u32)__cvta_generic_to_shared(sh);
    float* sbm = sh;                    // [8][64]
    float* sbp = sh + 512;              // [8][64]
    float* sAf = sh + 1024;             // 2 x [128][68]
    float* sBf = sh + 1024 + 2 * 8704;  // 2 x [128][68] (rows 0-63 proj, 64-127 phi)
    const u32 A0 = shb + 4096, B0 = shb + 4096 + 2 * 34816;

    int tid = threadIdx.x, wid = tid >> 5, lane = tid & 31;
    int g = lane >> 2, t4 = lane & 3;
    int warpM = wid & 3, warpN = wid >> 2;
    int e0 = blockIdx.x * 64, n0 = blockIdx.y * 128;

    for (int i = tid; i < MREL * 64; i += 256) {
        int m = i >> 6, c = i & 63;
        sbm[i] = bmax[m * DDIM + e0 + c];
        sbp[i] = bphi[m * DDIM + e0 + c];
    }

    auto stage = [&](int it) {
        int m = it >> 2, k0 = (it & 3) * 64, s = it & 1;
        const float* za = zs + (size_t)m * N * DDIM;
        const float* wb = g_wT + (size_t)m * 2 * 65536;
        u32 sa = A0 + s * 34816, sb = B0 + s * 34816;
#pragma unroll
        for (int j = 0; j < 8; j++) {
            int f = tid + j * 256;             // A: 2048 16B chunks
            int row = f >> 4, kq = f & 15;
            int nr = n0 + row; if (nr >= N) nr = N - 1;
            cpa16(sa + row * 272 + kq * 16, za + (size_t)nr * DDIM + k0 + kq * 4);
        }
#pragma unroll
        for (int j = 0; j < 8; j++) {
            int f = tid + j * 256;             // B: 2048 16B chunks
            int row = f >> 4, kq = f & 15;
            const float* src = wb + (row >= 64 ? 65536 : 0)
                               + (size_t)(e0 + (row & 63)) * 256 + k0 + kq * 4;
            cpa16(sb + row * 272 + kq * 16, src);
        }
    };

    stage(0); CP_COMMIT();

    float stP[32], stF1[32], stF2[32];
#pragma unroll
    for (int i = 0; i < 32; i++) { stP[i] = -3.0e38f; stF1[i] = 0.f; stF2[i] = 0.f; }

    float dP[2][4][4], dF[2][4][4];

    for (int it = 0; it < 32; it++) {
        int m = it >> 2, chunk = it & 3, s = it & 1;
        if (chunk == 0) {
#pragma unroll
            for (int mm = 0; mm < 2; mm++)
#pragma unroll
                for (int nn = 0; nn < 4; nn++)
#pragma unroll
                    for (int i = 0; i < 4; i++) { dP[mm][nn][i] = 0.f; dF[mm][nn][i] = 0.f; }
        }
        CP_WAIT0();
        __syncthreads();
        if (it + 1 < 32) { stage(it + 1); CP_COMMIT(); }

        const float* A  = sAf + s * 8704 + (warpM * 32 + g) * 68;
        const float* Bp = sBf + s * 8704 + (warpN * 32 + g) * 68;
        const float* Bf = Bp + 64 * 68;
#pragma unroll
        for (int ks = 0; ks < 8; ks++) {
            int kb = ks * 8 + t4;
            u32 a[2][4], bp[4][2], bf[4][2];
#pragma unroll
            for (int mm = 0; mm < 2; mm++) {
                const float* ar = A + mm * 16 * 68 + kb;
                a[mm][0] = f2tf(ar[0]);
                a[mm][1] = f2tf(ar[8 * 68]);
                a[mm][2] = f2tf(ar[4]);
                a[mm][3] = f2tf(ar[8 * 68 + 4]);
            }
#pragma unroll
            for (int nn = 0; nn < 4; nn++) {
                const float* bpr = Bp + nn * 8 * 68 + kb;
                bp[nn][0] = fasu(bpr[0]); bp[nn][1] = fasu(bpr[4]);
                const float* bfr = Bf + nn * 8 * 68 + kb;
                bf[nn][0] = fasu(bfr[0]); bf[nn][1] = fasu(bfr[4]);
            }
#pragma unroll
            for (int mm = 0; mm < 2; mm++)
#pragma unroll
                for (int nn = 0; nn < 4; nn++) {
                    mma8(dP[mm][nn], a[mm], bp[nn]);
                    mma8(dF[mm][nn], a[mm], bf[nn]);
                }
        }

        if (chunk == 3) {  // fold relation m
#pragma unroll
            for (int nn = 0; nn < 4; nn++) {
                int cb = m * 64 + warpN * 32 + nn * 8 + t4 * 2;
                float bm0 = sbm[cb], bm1 = sbm[cb + 1];
                float bp0 = sbp[cb], bp1 = sbp[cb + 1];
#pragma unroll
                for (int mm = 0; mm < 2; mm++) {
                    int ix = mm * 16 + nn * 4;
                    stP[ix + 0] = fmaxf(stP[ix + 0], dP[mm][nn][0] + bm0);
                    stP[ix + 1] = fmaxf(stP[ix + 1], dP[mm][nn][1] + bm1);
                    stP[ix + 2] = fmaxf(stP[ix + 2], dP[mm][nn][2] + bm0);
                    stP[ix + 3] = fmaxf(stP[ix + 3], dP[mm][nn][3] + bm1);
                    float v0 = dF[mm][nn][0] + bp0, v1 = dF[mm][nn][1] + bp1;
                    float v2 = dF[mm][nn][2] + bp0, v3 = dF[mm][nn][3] + bp1;
                    stF1[ix + 0] += v0; stF2[ix + 0] = fmaf(v0, v0, stF2[ix + 0]);
                    stF1[ix + 1] += v1; stF2[ix + 1] = fmaf(v1, v1, stF2[ix + 1]);
                    stF1[ix + 2] += v2; stF2[ix + 2] = fmaf(v2, v2, stF2[ix + 2]);
                    stF1[ix + 3] += v3; stF2[ix + 3] = fmaf(v3, v3, stF2[ix + 3]);
                }
            }
        }
    }

#pragma unroll
    for (int mm = 0; mm < 2; mm++) {
#pragma unroll
        for (int h = 0; h < 2; h++) {
            int n = n0 + warpM * 32 + mm * 16 + g + h * 8;
            if (n >= N) continue;
#pragma unroll
            for (int nn = 0; nn < 4; nn++) {
                int ix = mm * 16 + nn * 4 + h * 2;
                int e = e0 + warpN * 32 + nn * 8 + t4 * 2;
                *(float2*)(g_zmax + (size_t)n * DDIM + e) = make_float2(stP[ix], stP[ix + 1]);
                float a0 = 0.5f * (stF1[ix] * stF1[ix] - stF2[ix]);
                float a1 = 0.5f * (stF1[ix + 1] * stF1[ix + 1] - stF2[ix + 1]);
                *(float2*)(g_zagr + (size_t)n * DDIM + e) = make_float2(a0, a1);
            }
        }
    }
}

// ============================================================================
// Kernel 3: combine GEMM (K=768), A-side hi/lo split compensation (2 mmas):
// A fp32 in smem; ahi = rna(a), alo = a - ahi (fed raw; HW truncates).
// K-chunk 64, 2-stage cp.async. CTA 128 x 64; warps 4M x 2N.
// ============================================================================
__global__ void __launch_bounds__(256, 2) k_combine_mma(
        const float* __restrict__ bc, int N) {
    extern __shared__ float sh[];
    u32 shb = (u32)__cvta_generic_to_shared(sh);
    float* sAf = sh;                 // 2 x [128][68]
    float* sBf = sh + 2 * 8704;      // 2 x [64][68]
    const u32 A0 = shb, B0 = shb + 2 * 34816;

    int tid = threadIdx.x, wid = tid >> 5, lane = tid & 31;
    int g = lane >> 2, t4 = lane & 3;
    int warpM = wid & 3, warpN = wid >> 2;
    int e0 = blockIdx.x * 64, n0 = blockIdx.y * 128;

    auto stage = [&](int c) {
        int k0 = c * 64, s = c & 1;
        const float* src = (k0 < 256) ? g_zsum : (k0 < 512) ? g_zmax : g_zagr;
        int kc = k0 & 255;
        u32 sa = A0 + s * 34816, sb = B0 + s * 17408;
#pragma unroll
        for (int j = 0; j < 8; j++) {
            int f = tid + j * 256;           // A: 2048 chunks
            int row = f >> 4, kq = f & 15;
            int nr = n0 + row; if (nr >= N) nr = N - 1;
            cpa16(sa + row * 272 + kq * 16, src + (size_t)nr * DDIM + kc + kq * 4);
        }
#pragma unroll
        for (int j = 0; j < 4; j++) {
            int f = tid + j * 256;           // B: 1024 chunks
            int row = f >> 4, kq = f & 15;
            cpa16(sb + row * 272 + kq * 16, g_wcT + (size_t)(e0 + row) * 768 + k0 + kq * 4);
        }
    };

    stage(0); CP_COMMIT();

    float d[2][4][4];
#pragma unroll
    for (int mm = 0; mm < 2; mm++)
#pragma unroll
        for (int nn = 0; nn < 4; nn++)
#pragma unroll
            for (int i = 0; i < 4; i++) d[mm][nn][i] = 0.f;

    for (int c = 0; c < 12; c++) {
        int s = c & 1;
        CP_WAIT0();
        __syncthreads();
        if (c + 1 < 12) { stage(c + 1); CP_COMMIT(); }

        const float* A = sAf + s * 8704 + (warpM * 32 + g) * 68;
        const float* B = sBf + s * 4352 + (warpN * 32 + g) * 68;
#pragma unroll
        for (int ks = 0; ks < 8; ks++) {
            int kb = ks * 8 + t4;
            u32 ahi[2][4], alo[2][4], b[4][2];
#pragma unroll
            for (int mm = 0; mm < 2; mm++) {
                const float* ar = A + mm * 16 * 68 + kb;
                float r0 = ar[0], r1 = ar[8 * 68], r2 = ar[4], r3 = ar[8 * 68 + 4];
                ahi[mm][0] = f2tf(r0); alo[mm][0] = fasu(r0 - __uint_as_float(ahi[mm][0]));
                ahi[mm][1] = f2tf(r1); alo[mm][1] = fasu(r1 - __uint_as_float(ahi[mm][1]));
                ahi[mm][2] = f2tf(r2); alo[mm][2] = fasu(r2 - __uint_as_float(ahi[mm][2]));
                ahi[mm][3] = f2tf(r3); alo[mm][3] = fasu(r3 - __uint_as_float(ahi[mm][3]));
            }
#pragma unroll
            for (int nn = 0; nn < 4; nn++) {
                const float* br = B + nn * 8 * 68 + kb;
                b[nn][0] = fasu(br[0]); b[nn][1] = fasu(br[4]);
            }
#pragma unroll
            for (int mm = 0; mm < 2; mm++)
#pragma unroll
                for (int nn = 0; nn < 4; nn++) {
                    mma8(d[mm][nn], alo[mm], b[nn]);
                    mma8(d[mm][nn], ahi[mm], b[nn]);
                }
        }
    }

#pragma unroll
    for (int mm = 0; mm < 2; mm++) {
#pragma unroll
        for (int h = 0; h < 2; h++) {
            int n = n0 + warpM * 32 + mm * 16 + g + h * 8;
            if (n >= N) continue;
#pragma unroll
            for (int nn = 0; nn < 4; nn++) {
                int e = e0 + warpN * 32 + nn * 8 + t4 * 2;
                float b0 = __ldg(bc + e), b1 = __ldg(bc + e + 1);
                *(float2*)(g_zpre + (size_t)n * DDIM + e) =
                    make_float2(d[mm][nn][h * 2] + b0, d[mm][nn][h * 2 + 1] + b1);
            }
        }
    }
}

// ============================================================================
// Kernel 4: LayerNorm. One warp per node.
// ============================================================================
__global__ void k_ln(const float* __restrict__ gamma, const float* __restrict__ beta,
                     float* __restrict__ out, int N) {
    int tid = threadIdx.x;
    int lane = tid & 31, wid = tid >> 5;
    int n = blockIdx.x * (blockDim.x >> 5) + wid;
    if (n >= N) return;

    const float* p = g_zpre + (size_t)n * DDIM + lane * 8;
    float4 v0 = *(const float4*)p;
    float4 v1 = *(const float4*)(p + 4);
    float v[8] = {v0.x, v0.y, v0.z, v0.w, v1.x, v1.y, v1.z, v1.w};
    float s = 0.f, q = 0.f;
#pragma unroll
    for (int dd = 0; dd < 8; dd++) { s += v[dd]; q = fmaf(v[dd], v[dd], q); }
#pragma unroll
    for (int off = 16; off > 0; off >>= 1) {
        s += __shfl_xor_sync(0xffffffffu, s, off);
        q += __shfl_xor_sync(0xffffffffu, q, off);
    }
    float mean = s * (1.f / 256.f);
    float var = q * (1.f / 256.f) - mean * mean;
    float inv = rsqrtf(var + 1e-5f);

    const float* gp = gamma + lane * 8;
    const float* bp = beta + lane * 8;
    float4 g0 = *(const float4*)gp, g1 = *(const float4*)(gp + 4);
    float4 b0 = *(const float4*)bp, b1 = *(const float4*)(bp + 4);
    float gg[8] = {g0.x, g0.y, g0.z, g0.w, g1.x, g1.y, g1.z, g1.w};
    float bbv[8] = {b0.x, b0.y, b0.z, b0.w, b1.x, b1.y, b1.z, b1.w};
    float o[8];
#pragma unroll
    for (int dd = 0; dd < 8; dd++) o[dd] = fmaf((v[dd] - mean) * inv, gg[dd], bbv[dd]);

    float* qo = out + (size_t)n * DDIM + lane * 8;
    *(float4*)qo       = make_float4(o[0], o[1], o[2], o[3]);
    *(float4*)(qo + 4) = make_float4(o[4], o[5], o[6], o[7]);
}

// ============================================================================
extern "C" void kernel_launch(void* const* d_in, const int* in_sizes, int n_in,
                              void* d_out, int out_size) {
    const float* zs    = (const float*)d_in[0];
    const float* Wb    = (const float*)d_in[1];
    const float* bb    = (const float*)d_in[2];
    const float* Wmax  = (const float*)d_in[3];
    const float* bmax  = (const float*)d_in[4];
    const float* Wphi  = (const float*)d_in[5];
    const float* bphi  = (const float*)d_in[6];
    const float* Wc    = (const float*)d_in[7];
    const float* bc    = (const float*)d_in[8];
    const float* gamma = (const float*)d_in[9];
    const float* beta  = (const float*)d_in[10];
    float* out = (float*)d_out;

    int N = in_sizes[0] / (MREL * DDIM);
    int nt128 = (N + 127) / 128;

    cudaFuncSetAttribute(k_gate_zsum, cudaFuncAttributeMaxDynamicSharedMemorySize, 73728);
    cudaFuncSetAttribute(k_maxphi_mma, cudaFuncAttributeMaxDynamicSharedMemorySize, 143360);
    cudaFuncSetAttribute(k_combine_mma, cudaFuncAttributeMaxDynamicSharedMemorySize, 104448);

    k_wtrans<<<dim3(8, 8, 16), 256>>>(Wmax, Wphi);
    k_wctrans<<<dim3(24, 8), 256>>>(Wc);

    k_gate_zsum<<<592, 256, 73728>>>(zs, Wb, bb, N);

    k_maxphi_mma<<<dim3(4, nt128), 256, 143360>>>(zs, bmax, bphi, N);

    k_combine_mma<<<dim3(4, nt128), 256, 104448>>>(bc, N);

    k_ln<<<(N + 7) / 8, 256>>>(gamma, beta, out, N);
}